// round 1
// baseline (speedup 1.0000x reference)
#include <cuda_runtime.h>

#define NN 50000
#define EE 1600000
#define HH 128
#define OUTD 64
#define BN_EPS 1e-5f

// ---------------- device scratch (static, no allocation) ----------------
__device__ int   g_deg[NN];
__device__ int   g_off[NN + 1];
__device__ int   g_cur[NN];
__device__ int   g_csr[EE];
__device__ float g_agg[(size_t)NN * HH];
__device__ float g_y  [(size_t)NN * HH];
__device__ float g_h  [(size_t)NN * HH];
__device__ float g_sum[HH];
__device__ float g_sq [HH];

// ---------------- CSR build ----------------
__global__ void k_zero_deg() {
    int i = blockIdx.x * blockDim.x + threadIdx.x;
    if (i < NN) g_deg[i] = 0;
}

__global__ void k_hist(const int* __restrict__ dst) {
    int i = blockIdx.x * blockDim.x + threadIdx.x;
    if (i < EE) atomicAdd(&g_deg[dst[i]], 1);
}

// single-block exclusive scan over g_deg -> g_off, g_cur
__global__ void k_scan() {
    __shared__ int sh[1024];
    __shared__ int carry;
    int t = threadIdx.x;
    if (t == 0) carry = 0;
    __syncthreads();
    for (int base = 0; base < NN; base += 1024) {
        int i = base + t;
        int v = (i < NN) ? g_deg[i] : 0;
        sh[t] = v;
        __syncthreads();
        #pragma unroll
        for (int s = 1; s < 1024; s <<= 1) {
            int u = (t >= s) ? sh[t - s] : 0;
            __syncthreads();
            sh[t] += u;
            __syncthreads();
        }
        int excl = carry + sh[t] - v;
        if (i < NN) { g_off[i] = excl; g_cur[i] = excl; }
        __syncthreads();
        if (t == 0) carry += sh[1023];
        __syncthreads();
    }
    if (t == 0) g_off[NN] = carry;
}

__global__ void k_fill(const int* __restrict__ src, const int* __restrict__ dst) {
    int i = blockIdx.x * blockDim.x + threadIdx.x;
    if (i < EE) {
        int p = atomicAdd(&g_cur[dst[i]], 1);
        g_csr[p] = src[i];
    }
}

// ---------------- aggregation: scatter-mean as CSR gather-sum ----------------
// one block (128 threads) per node, channel-per-thread, fully coalesced loads
__global__ void k_agg(const float* __restrict__ xext, int use_h) {
    const float* __restrict__ xin = use_h ? g_h : xext;
    int n = blockIdx.x;
    int c = threadIdx.x;
    int s0 = g_off[n], s1 = g_off[n + 1];
    __shared__ int sid[128];
    float acc = 0.f;
    for (int base = s0; base < s1; base += 128) {
        int m = min(128, s1 - base);
        __syncthreads();
        if (c < m) sid[c] = g_csr[base + c];
        __syncthreads();
        #pragma unroll 8
        for (int j = 0; j < m; j++)
            acc += xin[(size_t)sid[j] * HH + c];
    }
    float d = (float)(s1 - s0);
    g_agg[(size_t)n * HH + c] = acc / fmaxf(d, 1.0f);
}

// ---------------- fused dual GEMM: y = agg@Wl^T + x@Wr^T + b (+ BN stats) ----------------
__global__ void k_zero_stats() {
    int t = threadIdx.x;
    if (t < HH) { g_sum[t] = 0.f; g_sq[t] = 0.f; }
}

template <int DOUT, bool STATS>
__global__ void __launch_bounds__(256)
k_gemm(const float* __restrict__ xext, int use_h,
       const float* __restrict__ Wl, const float* __restrict__ Wr,
       const float* __restrict__ bias, float* __restrict__ outext)
{
    constexpr int BM = 128, BK = 32, TN = 8;
    constexpr int CG = DOUT / TN;      // col groups (16 or 8)
    constexpr int RG = 256 / CG;       // row groups (16 or 32)
    constexpr int TM = BM / RG;        // rows per thread (8 or 4)

    __shared__ __align__(16) float As[BK][BM + 4];
    __shared__ __align__(16) float Bs[BK][DOUT + 4];
    __shared__ float ssum[DOUT];
    __shared__ float ssq [DOUT];

    const float* __restrict__ A2 = use_h ? g_h : xext;
    float* __restrict__ out = STATS ? g_y : outext;

    int t  = threadIdx.x;
    int cg = t % CG, rg = t / CG;
    int rowbase = blockIdx.x * BM;
    int col0 = cg * TN;

    float acc[TM][TN];
    #pragma unroll
    for (int i = 0; i < TM; i++)
        #pragma unroll
        for (int j = 0; j < TN; j++) acc[i][j] = 0.f;

    int ar = t >> 3;            // 0..31
    int kq = (t & 7) * 4;       // 0..28

    for (int kt = 0; kt < 8; kt++) {
        const float* __restrict__ Asrc = (kt < 4) ? g_agg : A2;
        const float* __restrict__ Wsrc = (kt < 4) ? Wl : Wr;
        int kb = (kt & 3) * BK;

        // load A tile 128x32 (transposed into As[k][row])
        #pragma unroll
        for (int it = 0; it < 4; it++) {
            int rloc = ar + it * 32;
            int r = rowbase + rloc;
            float4 v = make_float4(0.f, 0.f, 0.f, 0.f);
            if (r < NN) v = *(const float4*)&Asrc[(size_t)r * HH + kb + kq];
            As[kq + 0][rloc] = v.x;
            As[kq + 1][rloc] = v.y;
            As[kq + 2][rloc] = v.z;
            As[kq + 3][rloc] = v.w;
        }
        // load B tile 32xDOUT (Bs[k][o] = W[o][kb+k])
        #pragma unroll
        for (int it = 0; it < DOUT / 32; it++) {
            int o = ar + it * 32;
            float4 w = *(const float4*)&Wsrc[(size_t)o * HH + kb + kq];
            Bs[kq + 0][o] = w.x;
            Bs[kq + 1][o] = w.y;
            Bs[kq + 2][o] = w.z;
            Bs[kq + 3][o] = w.w;
        }
        __syncthreads();

        #pragma unroll
        for (int kk = 0; kk < BK; kk++) {
            float a_[TM], b_[TN];
            #pragma unroll
            for (int i = 0; i < TM; i += 4) {
                float4 v = *(const float4*)&As[kk][rg * TM + i];
                a_[i] = v.x; a_[i + 1] = v.y; a_[i + 2] = v.z; a_[i + 3] = v.w;
            }
            #pragma unroll
            for (int j = 0; j < TN; j += 4) {
                float4 v = *(const float4*)&Bs[kk][col0 + j];
                b_[j] = v.x; b_[j + 1] = v.y; b_[j + 2] = v.z; b_[j + 3] = v.w;
            }
            #pragma unroll
            for (int i = 0; i < TM; i++)
                #pragma unroll
                for (int j = 0; j < TN; j++)
                    acc[i][j] += a_[i] * b_[j];
        }
        __syncthreads();
    }

    // epilogue: bias, store, optional column stats for BN
    float bi[TN];
    #pragma unroll
    for (int j = 0; j < TN; j++) bi[j] = bias[col0 + j];

    if (STATS) {
        if (t < DOUT) { ssum[t] = 0.f; ssq[t] = 0.f; }
        __syncthreads();
        float ls[TN], lq[TN];
        #pragma unroll
        for (int j = 0; j < TN; j++) { ls[j] = 0.f; lq[j] = 0.f; }
        #pragma unroll
        for (int i = 0; i < TM; i++) {
            int r = rowbase + rg * TM + i;
            if (r < NN) {
                #pragma unroll
                for (int j = 0; j < TN; j++) {
                    float v = acc[i][j] + bi[j];
                    out[(size_t)r * DOUT + col0 + j] = v;
                    ls[j] += v;
                    lq[j] += v * v;
                }
            }
        }
        #pragma unroll
        for (int j = 0; j < TN; j++) {
            atomicAdd(&ssum[col0 + j], ls[j]);
            atomicAdd(&ssq [col0 + j], lq[j]);
        }
        __syncthreads();
        if (t < DOUT) {
            atomicAdd(&g_sum[t], ssum[t]);
            atomicAdd(&g_sq [t], ssq [t]);
        }
    } else {
        #pragma unroll
        for (int i = 0; i < TM; i++) {
            int r = rowbase + rg * TM + i;
            if (r < NN) {
                #pragma unroll
                for (int j = 0; j < TN; j++)
                    out[(size_t)r * DOUT + col0 + j] = acc[i][j] + bi[j];
            }
        }
    }
}

// ---------------- BN apply + ReLU: g_y -> g_h ----------------
__global__ void k_bn(const float* __restrict__ gamma, const float* __restrict__ beta) {
    int i = blockIdx.x * blockDim.x + threadIdx.x;
    if (i >= NN * HH) return;
    int o = i & (HH - 1);
    const float invN = 1.0f / (float)NN;
    float mu  = g_sum[o] * invN;
    float var = g_sq[o] * invN - mu * mu;
    float v = (g_y[i] - mu) * rsqrtf(var + BN_EPS) * gamma[o] + beta[o];
    g_h[i] = fmaxf(v, 0.f);
}

// ---------------- launch ----------------
extern "C" void kernel_launch(void* const* d_in, const int* in_sizes, int n_in,
                              void* d_out, int out_size)
{
    const float* x   = (const float*)d_in[0];
    const int*   ei  = (const int*)d_in[1];
    const int*   src = ei;
    const int*   dst = ei + EE;
    const float* Wl0 = (const float*)d_in[2];
    const float* Wr0 = (const float*)d_in[3];
    const float* b0  = (const float*)d_in[4];
    const float* g0  = (const float*)d_in[5];
    const float* be0 = (const float*)d_in[6];
    const float* Wl1 = (const float*)d_in[7];
    const float* Wr1 = (const float*)d_in[8];
    const float* b1  = (const float*)d_in[9];
    const float* g1  = (const float*)d_in[10];
    const float* be1 = (const float*)d_in[11];
    const float* Wl2 = (const float*)d_in[12];
    const float* Wr2 = (const float*)d_in[13];
    const float* b2  = (const float*)d_in[14];
    float* out = (float*)d_out;

    const int TPB = 256;
    const int gE  = (EE + TPB - 1) / TPB;
    const int gN  = (NN + TPB - 1) / TPB;
    const int gG  = (NN + 127) / 128;
    const int gBN = (NN * HH + TPB - 1) / TPB;

    // CSR build (reused by all 3 layers)
    k_zero_deg<<<gN, TPB>>>();
    k_hist<<<gE, TPB>>>(dst);
    k_scan<<<1, 1024>>>();
    k_fill<<<gE, TPB>>>(src, dst);

    // layer 0
    k_agg<<<NN, 128>>>(x, 0);
    k_zero_stats<<<1, 128>>>();
    k_gemm<HH, true><<<gG, 256>>>(x, 0, Wl0, Wr0, b0, nullptr);
    k_bn<<<gBN, TPB>>>(g0, be0);

    // layer 1
    k_agg<<<NN, 128>>>(nullptr, 1);
    k_zero_stats<<<1, 128>>>();
    k_gemm<HH, true><<<gG, 256>>>(nullptr, 1, Wl1, Wr1, b1, nullptr);
    k_bn<<<gBN, TPB>>>(g1, be1);

    // layer 2 (no BN, OUT=64), writes straight to d_out
    k_agg<<<NN, 128>>>(nullptr, 1);
    k_gemm<OUTD, false><<<gG, 256>>>(nullptr, 1, Wl2, Wr2, b2, out);
}

// round 2
// speedup vs baseline: 1.1556x; 1.1556x over previous
#include <cuda_runtime.h>

#define NN 50000
#define EE 1600000
#define HH 128
#define OUTD 64
#define BN_EPS 1e-5f

// ---------------- device scratch (static, no allocation) ----------------
__device__ int   g_deg[NN];
__device__ int   g_off[NN + 1];
__device__ int   g_cur[NN];
__device__ int   g_csr[EE];
__device__ float g_agg[(size_t)NN * HH];
__device__ float g_y  [(size_t)NN * HH];
__device__ float g_h  [(size_t)NN * HH];
__device__ float g_sum[HH];
__device__ float g_sq [HH];

// ---------------- CSR build ----------------
__global__ void k_zero_deg() {
    int i = blockIdx.x * blockDim.x + threadIdx.x;
    if (i < NN) g_deg[i] = 0;
}

__global__ void k_hist(const int* __restrict__ dst) {
    int i = blockIdx.x * blockDim.x + threadIdx.x;
    if (i < EE) atomicAdd(&g_deg[dst[i]], 1);
}

// single-block scan, thread-serial chunks + warp-shuffle block scan (2 barriers total)
__global__ void __launch_bounds__(1024) k_scan() {
    const int C = (NN + 1023) / 1024;   // 49 elems per thread
    int t = threadIdx.x;
    int lo = t * C, hi = min(lo + C, NN);
    int s = 0;
    for (int i = lo; i < hi; i++) s += g_deg[i];

    int lane = t & 31, wid = t >> 5;
    int v = s;
    #pragma unroll
    for (int d = 1; d < 32; d <<= 1) {
        int u = __shfl_up_sync(0xffffffffu, v, d);
        if (lane >= d) v += u;
    }
    __shared__ int wsum[32];
    if (lane == 31) wsum[wid] = v;
    __syncthreads();
    if (wid == 0) {
        int w = wsum[lane];
        #pragma unroll
        for (int d = 1; d < 32; d <<= 1) {
            int u = __shfl_up_sync(0xffffffffu, w, d);
            if (lane >= d) w += u;
        }
        wsum[lane] = w;
    }
    __syncthreads();
    int excl = v - s + (wid ? wsum[wid - 1] : 0);
    for (int i = lo; i < hi; i++) {
        g_off[i] = excl; g_cur[i] = excl;
        excl += g_deg[i];
    }
    if (t == 0) g_off[NN] = wsum[31];
}

__global__ void k_fill(const int* __restrict__ src, const int* __restrict__ dst) {
    int i = blockIdx.x * blockDim.x + threadIdx.x;
    if (i < EE) {
        int p = atomicAdd(&g_cur[dst[i]], 1);
        g_csr[p] = src[i];
    }
}

// ---------------- aggregation: warp per node, float4 per lane ----------------
// also zeroes BN-stat accumulators (block 0) so no separate zero kernel is needed
__global__ void __launch_bounds__(256) k_agg128(const float* __restrict__ xext, int use_h) {
    if (blockIdx.x == 0 && threadIdx.x < HH) {
        g_sum[threadIdx.x] = 0.f;
        g_sq [threadIdx.x] = 0.f;
    }
    const float* __restrict__ xin = use_h ? g_h : xext;
    int gw = (blockIdx.x * 256 + threadIdx.x) >> 5;
    if (gw >= NN) return;
    int lane = threadIdx.x & 31;
    int s0 = g_off[gw], s1 = g_off[gw + 1];
    const float* base = xin + lane * 4;
    float4 acc = make_float4(0.f, 0.f, 0.f, 0.f);
    for (int b = s0; b < s1; b += 32) {
        int m = s1 - b; if (m > 32) m = 32;
        int idx = (lane < m) ? g_csr[b + lane] : 0;
        #pragma unroll 4
        for (int j = 0; j < m; j++) {
            int sj = __shfl_sync(0xffffffffu, idx, j);
            float4 v = *(const float4*)(base + (size_t)sj * HH);
            acc.x += v.x; acc.y += v.y; acc.z += v.z; acc.w += v.w;
        }
    }
    float inv = 1.f / fmaxf((float)(s1 - s0), 1.f);
    acc.x *= inv; acc.y *= inv; acc.z *= inv; acc.w *= inv;
    *(float4*)&g_agg[(size_t)gw * HH + lane * 4] = acc;
}

// final layer: aggregate transformed 64-dim features (cols 0-63 of g_y),
// add self-branch (cols 64-127, bias already applied), write straight to d_out
__global__ void __launch_bounds__(256) k_agg64_add(float* __restrict__ out) {
    int gw = (blockIdx.x * 256 + threadIdx.x) >> 5;
    if (gw >= NN) return;
    int lane = threadIdx.x & 31;
    int s0 = g_off[gw], s1 = g_off[gw + 1];
    const float* base = g_y + lane * 2;
    float2 acc = make_float2(0.f, 0.f);
    for (int b = s0; b < s1; b += 32) {
        int m = s1 - b; if (m > 32) m = 32;
        int idx = (lane < m) ? g_csr[b + lane] : 0;
        #pragma unroll 4
        for (int j = 0; j < m; j++) {
            int sj = __shfl_sync(0xffffffffu, idx, j);
            float2 v = *(const float2*)(base + (size_t)sj * HH);
            acc.x += v.x; acc.y += v.y;
        }
    }
    float inv = 1.f / fmaxf((float)(s1 - s0), 1.f);
    float2 r = *(const float2*)&g_y[(size_t)gw * HH + 64 + lane * 2];
    float2 o = make_float2(acc.x * inv + r.x, acc.y * inv + r.y);
    *(float2*)&out[(size_t)gw * OUTD + lane * 2] = o;
}

// ---------------- fused dual GEMM (layers 0/1): y = agg@Wl^T + x@Wr^T + b, + BN stats ----------------
__global__ void __launch_bounds__(256)
k_gemm(const float* __restrict__ xext, int use_h,
       const float* __restrict__ Wl, const float* __restrict__ Wr,
       const float* __restrict__ bias)
{
    constexpr int BM = 128, BK = 32, TN = 8, TM = 8, CG = 16;

    __shared__ __align__(16) float As[BK][BM + 4];
    __shared__ __align__(16) float Bs[BK][HH + 4];
    __shared__ float ssum[HH];
    __shared__ float ssq [HH];

    const float* __restrict__ A2 = use_h ? g_h : xext;

    int t  = threadIdx.x;
    int cg = t % CG, rg = t / CG;
    int rowbase = blockIdx.x * BM;
    int col0 = cg * TN;

    float acc[TM][TN];
    #pragma unroll
    for (int i = 0; i < TM; i++)
        #pragma unroll
        for (int j = 0; j < TN; j++) acc[i][j] = 0.f;

    int ar = t >> 3;
    int kq = (t & 7) * 4;

    for (int kt = 0; kt < 8; kt++) {
        const float* __restrict__ Asrc = (kt < 4) ? g_agg : A2;
        const float* __restrict__ Wsrc = (kt < 4) ? Wl : Wr;
        int kb = (kt & 3) * BK;

        #pragma unroll
        for (int it = 0; it < 4; it++) {
            int rloc = ar + it * 32;
            int r = rowbase + rloc;
            float4 v = make_float4(0.f, 0.f, 0.f, 0.f);
            if (r < NN) v = *(const float4*)&Asrc[(size_t)r * HH + kb + kq];
            As[kq + 0][rloc] = v.x;
            As[kq + 1][rloc] = v.y;
            As[kq + 2][rloc] = v.z;
            As[kq + 3][rloc] = v.w;
        }
        #pragma unroll
        for (int it = 0; it < 4; it++) {
            int o = ar + it * 32;
            float4 w = *(const float4*)&Wsrc[(size_t)o * HH + kb + kq];
            Bs[kq + 0][o] = w.x;
            Bs[kq + 1][o] = w.y;
            Bs[kq + 2][o] = w.z;
            Bs[kq + 3][o] = w.w;
        }
        __syncthreads();

        #pragma unroll
        for (int kk = 0; kk < BK; kk++) {
            float a_[TM], b_[TN];
            #pragma unroll
            for (int i = 0; i < TM; i += 4) {
                float4 v = *(const float4*)&As[kk][rg * TM + i];
                a_[i] = v.x; a_[i + 1] = v.y; a_[i + 2] = v.z; a_[i + 3] = v.w;
            }
            #pragma unroll
            for (int j = 0; j < TN; j += 4) {
                float4 v = *(const float4*)&Bs[kk][col0 + j];
                b_[j] = v.x; b_[j + 1] = v.y; b_[j + 2] = v.z; b_[j + 3] = v.w;
            }
            #pragma unroll
            for (int i = 0; i < TM; i++)
                #pragma unroll
                for (int j = 0; j < TN; j++)
                    acc[i][j] += a_[i] * b_[j];
        }
        __syncthreads();
    }

    float bi[TN];
    #pragma unroll
    for (int j = 0; j < TN; j++) bi[j] = bias[col0 + j];

    if (t < HH) { ssum[t] = 0.f; ssq[t] = 0.f; }
    __syncthreads();
    float ls[TN], lq[TN];
    #pragma unroll
    for (int j = 0; j < TN; j++) { ls[j] = 0.f; lq[j] = 0.f; }
    #pragma unroll
    for (int i = 0; i < TM; i++) {
        int r = rowbase + rg * TM + i;
        if (r < NN) {
            #pragma unroll
            for (int j = 0; j < TN; j++) {
                float v = acc[i][j] + bi[j];
                g_y[(size_t)r * HH + col0 + j] = v;
                ls[j] += v;
                lq[j] += v * v;
            }
        }
    }
    #pragma unroll
    for (int j = 0; j < TN; j++) {
        atomicAdd(&ssum[col0 + j], ls[j]);
        atomicAdd(&ssq [col0 + j], lq[j]);
    }
    __syncthreads();
    if (t < HH) {
        atomicAdd(&g_sum[t], ssum[t]);
        atomicAdd(&g_sq [t], ssq [t]);
    }
}

// ---------------- layer-2 GEMM (transform-first): g_y[:,0:64]=h@Wl2^T, g_y[:,64:128]=h@Wr2^T+b2 ----------------
__global__ void __launch_bounds__(256)
k_gemm_l2(const float* __restrict__ Wl, const float* __restrict__ Wr,
          const float* __restrict__ bias)
{
    constexpr int BM = 128, BK = 32, TN = 8, TM = 8, CG = 16;

    __shared__ __align__(16) float As[BK][BM + 4];
    __shared__ __align__(16) float Bs[BK][HH + 4];

    int t  = threadIdx.x;
    int cg = t % CG, rg = t / CG;
    int rowbase = blockIdx.x * BM;
    int col0 = cg * TN;

    float acc[TM][TN];
    #pragma unroll
    for (int i = 0; i < TM; i++)
        #pragma unroll
        for (int j = 0; j < TN; j++) acc[i][j] = 0.f;

    int ar = t >> 3;
    int kq = (t & 7) * 4;

    for (int kt = 0; kt < 4; kt++) {
        int kb = kt * BK;
        #pragma unroll
        for (int it = 0; it < 4; it++) {
            int rloc = ar + it * 32;
            int r = rowbase + rloc;
            float4 v = make_float4(0.f, 0.f, 0.f, 0.f);
            if (r < NN) v = *(const float4*)&g_h[(size_t)r * HH + kb + kq];
            As[kq + 0][rloc] = v.x;
            As[kq + 1][rloc] = v.y;
            As[kq + 2][rloc] = v.z;
            As[kq + 3][rloc] = v.w;
        }
        #pragma unroll
        for (int it = 0; it < 4; it++) {
            int o = ar + it * 32;                       // 0..127
            const float* __restrict__ Wsrc = (o < OUTD) ? Wl : Wr;
            int orow = o & (OUTD - 1);
            float4 w = *(const float4*)&Wsrc[(size_t)orow * HH + kb + kq];
            Bs[kq + 0][o] = w.x;
            Bs[kq + 1][o] = w.y;
            Bs[kq + 2][o] = w.z;
            Bs[kq + 3][o] = w.w;
        }
        __syncthreads();

        #pragma unroll
        for (int kk = 0; kk < BK; kk++) {
            float a_[TM], b_[TN];
            #pragma unroll
            for (int i = 0; i < TM; i += 4) {
                float4 v = *(const float4*)&As[kk][rg * TM + i];
                a_[i] = v.x; a_[i + 1] = v.y; a_[i + 2] = v.z; a_[i + 3] = v.w;
            }
            #pragma unroll
            for (int j = 0; j < TN; j += 4) {
                float4 v = *(const float4*)&Bs[kk][col0 + j];
                b_[j] = v.x; b_[j + 1] = v.y; b_[j + 2] = v.z; b_[j + 3] = v.w;
            }
            #pragma unroll
            for (int i = 0; i < TM; i++)
                #pragma unroll
                for (int j = 0; j < TN; j++)
                    acc[i][j] += a_[i] * b_[j];
        }
        __syncthreads();
    }

    #pragma unroll
    for (int i = 0; i < TM; i++) {
        int r = rowbase + rg * TM + i;
        if (r < NN) {
            #pragma unroll
            for (int j = 0; j < TN; j++) {
                int col = col0 + j;
                float bv = (col >= OUTD) ? bias[col - OUTD] : 0.f;
                g_y[(size_t)r * HH + col] = acc[i][j] + bv;
            }
        }
    }
}

// ---------------- BN apply + ReLU: g_y -> g_h (float4) ----------------
__global__ void k_bn4(const float* __restrict__ gamma, const float* __restrict__ beta) {
    int i = blockIdx.x * blockDim.x + threadIdx.x;
    if (i >= NN * HH / 4) return;
    int o = (i & 31) * 4;
    const float invN = 1.0f / (float)NN;
    float4 y = *(const float4*)&g_y[(size_t)i * 4];
    float4 r;
    float mu, var, s;
    mu = g_sum[o + 0] * invN; var = g_sq[o + 0] * invN - mu * mu; s = rsqrtf(var + BN_EPS) * gamma[o + 0];
    r.x = fmaxf((y.x - mu) * s + beta[o + 0], 0.f);
    mu = g_sum[o + 1] * invN; var = g_sq[o + 1] * invN - mu * mu; s = rsqrtf(var + BN_EPS) * gamma[o + 1];
    r.y = fmaxf((y.y - mu) * s + beta[o + 1], 0.f);
    mu = g_sum[o + 2] * invN; var = g_sq[o + 2] * invN - mu * mu; s = rsqrtf(var + BN_EPS) * gamma[o + 2];
    r.z = fmaxf((y.z - mu) * s + beta[o + 2], 0.f);
    mu = g_sum[o + 3] * invN; var = g_sq[o + 3] * invN - mu * mu; s = rsqrtf(var + BN_EPS) * gamma[o + 3];
    r.w = fmaxf((y.w - mu) * s + beta[o + 3], 0.f);
    *(float4*)&g_h[(size_t)i * 4] = r;
}

// ---------------- launch ----------------
extern "C" void kernel_launch(void* const* d_in, const int* in_sizes, int n_in,
                              void* d_out, int out_size)
{
    const float* x   = (const float*)d_in[0];
    const int*   ei  = (const int*)d_in[1];
    const int*   src = ei;
    const int*   dst = ei + EE;
    const float* Wl0 = (const float*)d_in[2];
    const float* Wr0 = (const float*)d_in[3];
    const float* b0  = (const float*)d_in[4];
    const float* g0  = (const float*)d_in[5];
    const float* be0 = (const float*)d_in[6];
    const float* Wl1 = (const float*)d_in[7];
    const float* Wr1 = (const float*)d_in[8];
    const float* b1  = (const float*)d_in[9];
    const float* g1  = (const float*)d_in[10];
    const float* be1 = (const float*)d_in[11];
    const float* Wl2 = (const float*)d_in[12];
    const float* Wr2 = (const float*)d_in[13];
    const float* b2  = (const float*)d_in[14];
    float* out = (float*)d_out;

    const int TPB = 256;
    const int gE  = (EE + TPB - 1) / TPB;
    const int gN  = (NN + TPB - 1) / TPB;
    const int gG  = (NN + 127) / 128;
    const int gW  = (NN * 32 + TPB - 1) / TPB;      // warp-per-node grids
    const int gBN = (NN * HH / 4 + TPB - 1) / TPB;

    // CSR build (reused by all 3 layers)
    k_zero_deg<<<gN, TPB>>>();
    k_hist<<<gE, TPB>>>(dst);
    k_scan<<<1, 1024>>>();
    k_fill<<<gE, TPB>>>(src, dst);

    // layer 0
    k_agg128<<<gW, TPB>>>(x, 0);
    k_gemm<<<gG, TPB>>>(x, 0, Wl0, Wr0, b0);
    k_bn4<<<gBN, TPB>>>(g0, be0);

    // layer 1
    k_agg128<<<gW, TPB>>>(nullptr, 1);
    k_gemm<<<gG, TPB>>>(nullptr, 1, Wl1, Wr1, b1);
    k_bn4<<<gBN, TPB>>>(g1, be1);

    // layer 2: transform first, then 64-dim aggregate + add, straight to d_out
    k_gemm_l2<<<gG, TPB>>>(Wl2, Wr2, b2);
    k_agg64_add<<<gW, TPB>>>(out);
}

// round 4
// speedup vs baseline: 1.6663x; 1.4420x over previous
#include <cuda_runtime.h>
#include <cstdint>

#define NN 50000
#define EE 1600000
#define HH 128
#define OUTD 64
#define BN_EPS 1e-5f

// ---------------- device scratch (static, no allocation) ----------------
__device__ int   g_deg[NN];
__device__ int   g_off[NN + 1];
__device__ int   g_cur[NN];
__device__ int   g_csr[EE];
__device__ float g_agg[(size_t)NN * HH];
__device__ float g_y  [(size_t)NN * HH];
__device__ float g_h  [(size_t)NN * HH];
__device__ float g_sum[HH];
__device__ float g_sq [HH];

// ---------------- CSR build ----------------
__global__ void k_zero_deg() {
    int i = blockIdx.x * blockDim.x + threadIdx.x;
    if (i < NN) g_deg[i] = 0;
}

__global__ void k_hist(const int* __restrict__ dst) {
    int i = blockIdx.x * blockDim.x + threadIdx.x;
    if (i < EE) atomicAdd(&g_deg[dst[i]], 1);
}

__global__ void __launch_bounds__(1024) k_scan() {
    const int C = (NN + 1023) / 1024;
    int t = threadIdx.x;
    int lo = t * C, hi = min(lo + C, NN);
    int s = 0;
    for (int i = lo; i < hi; i++) s += g_deg[i];

    int lane = t & 31, wid = t >> 5;
    int v = s;
    #pragma unroll
    for (int d = 1; d < 32; d <<= 1) {
        int u = __shfl_up_sync(0xffffffffu, v, d);
        if (lane >= d) v += u;
    }
    __shared__ int wsum[32];
    if (lane == 31) wsum[wid] = v;
    __syncthreads();
    if (wid == 0) {
        int w = wsum[lane];
        #pragma unroll
        for (int d = 1; d < 32; d <<= 1) {
            int u = __shfl_up_sync(0xffffffffu, w, d);
            if (lane >= d) w += u;
        }
        wsum[lane] = w;
    }
    __syncthreads();
    int excl = v - s + (wid ? wsum[wid - 1] : 0);
    for (int i = lo; i < hi; i++) {
        g_off[i] = excl; g_cur[i] = excl;
        excl += g_deg[i];
    }
    if (t == 0) g_off[NN] = wsum[31];
}

__global__ void k_fill(const int* __restrict__ src, const int* __restrict__ dst) {
    int i = blockIdx.x * blockDim.x + threadIdx.x;
    if (i < EE) {
        int p = atomicAdd(&g_cur[dst[i]], 1);
        g_csr[p] = src[i];
    }
}

// ---------------- aggregation: warp per node, float4 per lane ----------------
__global__ void __launch_bounds__(256) k_agg128(const float* __restrict__ xext, int use_h) {
    if (blockIdx.x == 0 && threadIdx.x < HH) {
        g_sum[threadIdx.x] = 0.f;
        g_sq [threadIdx.x] = 0.f;
    }
    const float* __restrict__ xin = use_h ? g_h : xext;
    int gw = (blockIdx.x * 256 + threadIdx.x) >> 5;
    if (gw >= NN) return;
    int lane = threadIdx.x & 31;
    int s0 = g_off[gw], s1 = g_off[gw + 1];
    const float* base = xin + lane * 4;
    float4 acc = make_float4(0.f, 0.f, 0.f, 0.f);
    for (int b = s0; b < s1; b += 32) {
        int m = s1 - b; if (m > 32) m = 32;
        int idx = (lane < m) ? g_csr[b + lane] : 0;
        #pragma unroll 4
        for (int j = 0; j < m; j++) {
            int sj = __shfl_sync(0xffffffffu, idx, j);
            float4 v = *(const float4*)(base + (size_t)sj * HH);
            acc.x += v.x; acc.y += v.y; acc.z += v.z; acc.w += v.w;
        }
    }
    float inv = 1.f / fmaxf((float)(s1 - s0), 1.f);
    acc.x *= inv; acc.y *= inv; acc.z *= inv; acc.w *= inv;
    *(float4*)&g_agg[(size_t)gw * HH + lane * 4] = acc;
}

// final layer: aggregate transformed 64-dim features (cols 0-63 of g_y),
// add self-branch (cols 64-127, bias applied), write to d_out
__global__ void __launch_bounds__(256) k_agg64_add(float* __restrict__ out) {
    int gw = (blockIdx.x * 256 + threadIdx.x) >> 5;
    if (gw >= NN) return;
    int lane = threadIdx.x & 31;
    int s0 = g_off[gw], s1 = g_off[gw + 1];
    const float* base = g_y + lane * 2;
    float2 acc = make_float2(0.f, 0.f);
    for (int b = s0; b < s1; b += 32) {
        int m = s1 - b; if (m > 32) m = 32;
        int idx = (lane < m) ? g_csr[b + lane] : 0;
        #pragma unroll 4
        for (int j = 0; j < m; j++) {
            int sj = __shfl_sync(0xffffffffu, idx, j);
            float2 v = *(const float2*)(base + (size_t)sj * HH);
            acc.x += v.x; acc.y += v.y;
        }
    }
    float inv = 1.f / fmaxf((float)(s1 - s0), 1.f);
    float2 r = *(const float2*)&g_y[(size_t)gw * HH + 64 + lane * 2];
    float2 o = make_float2(acc.x * inv + r.x, acc.y * inv + r.y);
    *(float2*)&out[(size_t)gw * OUTD + lane * 2] = o;
}

// ---------------- tf32 mma.sync GEMM ----------------
__device__ __forceinline__ uint32_t f2tf32(float f) {
    uint32_t r;
    asm("cvt.rna.tf32.f32 %0, %1;" : "=r"(r) : "f"(f));
    return r;
}

__device__ __forceinline__ void mma_16x8x8(float* c, const uint32_t* a, const uint32_t* b) {
    asm volatile(
        "mma.sync.aligned.m16n8k8.row.col.f32.tf32.tf32.f32 "
        "{%0,%1,%2,%3}, {%4,%5,%6,%7}, {%8,%9}, {%0,%1,%2,%3};"
        : "+f"(c[0]), "+f"(c[1]), "+f"(c[2]), "+f"(c[3])
        : "r"(a[0]), "r"(a[1]), "r"(a[2]), "r"(a[3]), "r"(b[0]), "r"(b[1]));
}

// Block: 256 threads = 8 warps (2 row x 4 col), tile 128x128, BK=32.
// Layers 0/1 (KCH=8, L2=false): g_y = [g_agg | A2] @ [Wl|Wr]^T + b      (K=256)
// Layer  2  (KCH=4, L2=true):   g_y = A2 @ [Wl2 ; Wr2]^T (N-concat), +b2 on cols>=64 (K=128)
template <int KCH, bool L2>
__global__ void __launch_bounds__(256)
k_gemm_mma(const float* __restrict__ xext, int use_h,
           const float* __restrict__ Wl, const float* __restrict__ Wr,
           const float* __restrict__ bias)
{
    constexpr int BK = 32, LDS_ = BK + 4;

    __shared__ uint32_t As[128 * LDS_];
    __shared__ uint32_t Bs[128 * LDS_];
    __shared__ float sbias[HH];

    const float* __restrict__ A2 = use_h ? g_h : xext;

    int tid = threadIdx.x;
    int wid = tid >> 5, lane = tid & 31;
    int wm = (wid & 1) * 64;        // warp row offset
    int wn = (wid >> 1) * 32;       // warp col offset
    int gid = lane >> 2;            // 0..7
    int tq  = lane & 3;             // 0..3
    int rowbase = blockIdx.x * 128;

    if (tid < HH) {
        if (L2) sbias[tid] = (tid >= OUTD) ? bias[tid - OUTD] : 0.f;
        else    sbias[tid] = bias[tid];
    }

    float c[4][4][4];
    #pragma unroll
    for (int i = 0; i < 4; i++)
        #pragma unroll
        for (int j = 0; j < 4; j++)
            #pragma unroll
            for (int k = 0; k < 4; k++) c[i][j][k] = 0.f;

    int lr = tid >> 3;              // 0..31 (load row)
    int lk = (tid & 7) * 4;         // 0,4,...,28 (load k)

    for (int kc = 0; kc < KCH; kc++) {
        const float* __restrict__ Asrc;
        int kb;
        if (L2) { Asrc = A2; kb = kc * BK; }
        else    { Asrc = (kc < 4) ? g_agg : A2; kb = (kc & 3) * BK; }

        #pragma unroll
        for (int it = 0; it < 4; it++) {
            int row = lr + it * 32;
            int r = rowbase + row;
            float4 v = make_float4(0.f, 0.f, 0.f, 0.f);
            if (r < NN) v = *(const float4*)&Asrc[(size_t)r * HH + kb + lk];
            uint32_t* d = &As[row * LDS_ + lk];
            d[0] = f2tf32(v.x); d[1] = f2tf32(v.y); d[2] = f2tf32(v.z); d[3] = f2tf32(v.w);
        }
        #pragma unroll
        for (int it = 0; it < 4; it++) {
            int n = lr + it * 32;
            const float* __restrict__ Wsrc;
            int wrow;
            if (L2) { Wsrc = (n < OUTD) ? Wl : Wr; wrow = n & (OUTD - 1); }
            else    { Wsrc = (kc < 4) ? Wl : Wr;   wrow = n; }
            float4 w = *(const float4*)&Wsrc[(size_t)wrow * HH + kb + lk];
            uint32_t* d = &Bs[n * LDS_ + lk];
            d[0] = f2tf32(w.x); d[1] = f2tf32(w.y); d[2] = f2tf32(w.z); d[3] = f2tf32(w.w);
        }
        __syncthreads();

        #pragma unroll
        for (int ks = 0; ks < BK / 8; ks++) {
            int k0 = ks * 8;
            uint32_t a[4][4], b[4][2];
            #pragma unroll
            for (int mi = 0; mi < 4; mi++) {
                const uint32_t* p0 = &As[(wm + mi * 16 + gid) * LDS_ + k0 + tq];
                const uint32_t* p1 = &As[(wm + mi * 16 + 8 + gid) * LDS_ + k0 + tq];
                a[mi][0] = p0[0]; a[mi][1] = p1[0];
                a[mi][2] = p0[4]; a[mi][3] = p1[4];
            }
            #pragma unroll
            for (int nj = 0; nj < 4; nj++) {
                const uint32_t* p = &Bs[(wn + nj * 8 + gid) * LDS_ + k0 + tq];
                b[nj][0] = p[0]; b[nj][1] = p[4];
            }
            #pragma unroll
            for (int mi = 0; mi < 4; mi++)
                #pragma unroll
                for (int nj = 0; nj < 4; nj++)
                    mma_16x8x8(c[mi][nj], a[mi], b[nj]);
        }
        __syncthreads();
    }

    // epilogue: bias + store (float2 per fragment row)
    #pragma unroll
    for (int mi = 0; mi < 4; mi++) {
        int r0 = rowbase + wm + mi * 16 + gid;
        int r1 = r0 + 8;
        #pragma unroll
        for (int nj = 0; nj < 4; nj++) {
            int col = wn + nj * 8 + tq * 2;
            float2 b2v = make_float2(sbias[col], sbias[col + 1]);
            if (r0 < NN) {
                float2 v = make_float2(c[mi][nj][0] + b2v.x, c[mi][nj][1] + b2v.y);
                *(float2*)&g_y[(size_t)r0 * HH + col] = v;
            }
            if (r1 < NN) {
                float2 v = make_float2(c[mi][nj][2] + b2v.x, c[mi][nj][3] + b2v.y);
                *(float2*)&g_y[(size_t)r1 * HH + col] = v;
            }
        }
    }
}

// ---------------- BN stats over g_y columns ----------------
__global__ void __launch_bounds__(256) k_stats() {
    int wid = threadIdx.x >> 5, lane = threadIdx.x & 31;
    int gw = blockIdx.x * 8 + wid;
    const int NW = 256 * 8;
    float4 s = make_float4(0.f, 0.f, 0.f, 0.f);
    float4 q = make_float4(0.f, 0.f, 0.f, 0.f);
    for (int r = gw; r < NN; r += NW) {
        float4 v = *(const float4*)&g_y[(size_t)r * HH + lane * 4];
        s.x += v.x; s.y += v.y; s.z += v.z; s.w += v.w;
        q.x += v.x * v.x; q.y += v.y * v.y; q.z += v.z * v.z; q.w += v.w * v.w;
    }
    __shared__ float ss[HH], sq[HH];
    if (threadIdx.x < HH) { ss[threadIdx.x] = 0.f; sq[threadIdx.x] = 0.f; }
    __syncthreads();
    int c = lane * 4;
    atomicAdd(&ss[c + 0], s.x); atomicAdd(&ss[c + 1], s.y);
    atomicAdd(&ss[c + 2], s.z); atomicAdd(&ss[c + 3], s.w);
    atomicAdd(&sq[c + 0], q.x); atomicAdd(&sq[c + 1], q.y);
    atomicAdd(&sq[c + 2], q.z); atomicAdd(&sq[c + 3], q.w);
    __syncthreads();
    if (threadIdx.x < HH) {
        atomicAdd(&g_sum[threadIdx.x], ss[threadIdx.x]);
        atomicAdd(&g_sq [threadIdx.x], sq[threadIdx.x]);
    }
}

// ---------------- BN apply + ReLU: g_y -> g_h (float4) ----------------
__global__ void k_bn4(const float* __restrict__ gamma, const float* __restrict__ beta) {
    int i = blockIdx.x * blockDim.x + threadIdx.x;
    if (i >= NN * HH / 4) return;
    int o = (i & 31) * 4;
    const float invN = 1.0f / (float)NN;
    float4 y = *(const float4*)&g_y[(size_t)i * 4];
    float4 r;
    float mu, var, s;
    mu = g_sum[o + 0] * invN; var = g_sq[o + 0] * invN - mu * mu; s = rsqrtf(var + BN_EPS) * gamma[o + 0];
    r.x = fmaxf((y.x - mu) * s + beta[o + 0], 0.f);
    mu = g_sum[o + 1] * invN; var = g_sq[o + 1] * invN - mu * mu; s = rsqrtf(var + BN_EPS) * gamma[o + 1];
    r.y = fmaxf((y.y - mu) * s + beta[o + 1], 0.f);
    mu = g_sum[o + 2] * invN; var = g_sq[o + 2] * invN - mu * mu; s = rsqrtf(var + BN_EPS) * gamma[o + 2];
    r.z = fmaxf((y.z - mu) * s + beta[o + 2], 0.f);
    mu = g_sum[o + 3] * invN; var = g_sq[o + 3] * invN - mu * mu; s = rsqrtf(var + BN_EPS) * gamma[o + 3];
    r.w = fmaxf((y.w - mu) * s + beta[o + 3], 0.f);
    *(float4*)&g_h[(size_t)i * 4] = r;
}

// ---------------- launch ----------------
extern "C" void kernel_launch(void* const* d_in, const int* in_sizes, int n_in,
                              void* d_out, int out_size)
{
    const float* x   = (const float*)d_in[0];
    const int*   ei  = (const int*)d_in[1];
    const int*   src = ei;
    const int*   dst = ei + EE;
    const float* Wl0 = (const float*)d_in[2];
    const float* Wr0 = (const float*)d_in[3];
    const float* b0  = (const float*)d_in[4];
    const float* g0  = (const float*)d_in[5];
    const float* be0 = (const float*)d_in[6];
    const float* Wl1 = (const float*)d_in[7];
    const float* Wr1 = (const float*)d_in[8];
    const float* b1  = (const float*)d_in[9];
    const float* g1  = (const float*)d_in[10];
    const float* be1 = (const float*)d_in[11];
    const float* Wl2 = (const float*)d_in[12];
    const float* Wr2 = (const float*)d_in[13];
    const float* b2  = (const float*)d_in[14];
    float* out = (float*)d_out;

    const int TPB = 256;
    const int gE  = (EE + TPB - 1) / TPB;
    const int gN  = (NN + TPB - 1) / TPB;
    const int gG  = (NN + 127) / 128;
    const int gW  = (NN * 32 + TPB - 1) / TPB;
    const int gBN = (NN * HH / 4 + TPB - 1) / TPB;

    // CSR build (reused by all 3 layers)
    k_zero_deg<<<gN, TPB>>>();
    k_hist<<<gE, TPB>>>(dst);
    k_scan<<<1, 1024>>>();
    k_fill<<<gE, TPB>>>(src, dst);

    // layer 0
    k_agg128<<<gW, TPB>>>(x, 0);
    k_gemm_mma<8, false><<<gG, TPB>>>(x, 0, Wl0, Wr0, b0);
    k_stats<<<256, TPB>>>();
    k_bn4<<<gBN, TPB>>>(g0, be0);

    // layer 1
    k_agg128<<<gW, TPB>>>(nullptr, 1);
    k_gemm_mma<8, false><<<gG, TPB>>>(nullptr, 1, Wl1, Wr1, b1);
    k_stats<<<256, TPB>>>();
    k_bn4<<<gBN, TPB>>>(g1, be1);

    // layer 2: transform first (N-concat dual GEMM), then 64-dim aggregate + add
    k_gemm_mma<4, true><<<gG, TPB>>>(nullptr, 1, Wl2, Wr2, b2);
    k_agg64_add<<<gW, TPB>>>(out);
}

// round 5
// speedup vs baseline: 1.8296x; 1.0980x over previous
#include <cuda_runtime.h>
#include <cuda_fp16.h>
#include <cstdint>

#define NN 50000
#define EE 1600000
#define HH 128
#define OUTD 64
#define BN_EPS 1e-5f

// ---------------- device scratch (static, no allocation) ----------------
__device__ int   g_deg[NN];
__device__ int   g_off[NN + 1];
__device__ int   g_cur[NN];
__device__ int   g_csr[EE];
__device__ float g_agg[(size_t)NN * HH];
__device__ float g_y  [(size_t)NN * HH];
__device__ float g_h  [(size_t)NN * HH];
__device__ float g_sum[HH];
__device__ float g_sq [HH];

// ---------------- CSR build ----------------
__global__ void k_zero_deg() {
    int i = blockIdx.x * blockDim.x + threadIdx.x;
    if (i < NN) g_deg[i] = 0;
}

__global__ void k_hist(const int* __restrict__ dst) {
    int i = blockIdx.x * blockDim.x + threadIdx.x;
    if (i < EE) atomicAdd(&g_deg[dst[i]], 1);
}

__global__ void __launch_bounds__(1024) k_scan() {
    const int C = (NN + 1023) / 1024;
    int t = threadIdx.x;
    int lo = t * C, hi = min(lo + C, NN);
    int s = 0;
    for (int i = lo; i < hi; i++) s += g_deg[i];

    int lane = t & 31, wid = t >> 5;
    int v = s;
    #pragma unroll
    for (int d = 1; d < 32; d <<= 1) {
        int u = __shfl_up_sync(0xffffffffu, v, d);
        if (lane >= d) v += u;
    }
    __shared__ int wsum[32];
    if (lane == 31) wsum[wid] = v;
    __syncthreads();
    if (wid == 0) {
        int w = wsum[lane];
        #pragma unroll
        for (int d = 1; d < 32; d <<= 1) {
            int u = __shfl_up_sync(0xffffffffu, w, d);
            if (lane >= d) w += u;
        }
        wsum[lane] = w;
    }
    __syncthreads();
    int excl = v - s + (wid ? wsum[wid - 1] : 0);
    for (int i = lo; i < hi; i++) {
        g_off[i] = excl; g_cur[i] = excl;
        excl += g_deg[i];
    }
    if (t == 0) g_off[NN] = wsum[31];
}

__global__ void k_fill(const int* __restrict__ src, const int* __restrict__ dst) {
    int i = blockIdx.x * blockDim.x + threadIdx.x;
    if (i < EE) {
        int p = atomicAdd(&g_cur[dst[i]], 1);
        g_csr[p] = src[i];
    }
}

// ---------------- aggregation: warp per node, float4 per lane, dual accumulators ----------------
__global__ void __launch_bounds__(256) k_agg128(const float* __restrict__ xext, int use_h) {
    if (blockIdx.x == 0 && threadIdx.x < HH) {
        g_sum[threadIdx.x] = 0.f;
        g_sq [threadIdx.x] = 0.f;
    }
    const float* __restrict__ xin = use_h ? g_h : xext;
    int gw = (blockIdx.x * 256 + threadIdx.x) >> 5;
    if (gw >= NN) return;
    int lane = threadIdx.x & 31;
    int s0 = g_off[gw], s1 = g_off[gw + 1];
    const float* base = xin + lane * 4;
    float4 a0 = make_float4(0.f, 0.f, 0.f, 0.f);
    float4 a1 = make_float4(0.f, 0.f, 0.f, 0.f);
    for (int b = s0; b < s1; b += 32) {
        int m = s1 - b; if (m > 32) m = 32;
        int idx = (lane < m) ? g_csr[b + lane] : 0;
        int j = 0;
        #pragma unroll 4
        for (; j + 2 <= m; j += 2) {
            int sa = __shfl_sync(0xffffffffu, idx, j);
            int sb = __shfl_sync(0xffffffffu, idx, j + 1);
            float4 v0 = *(const float4*)(base + (size_t)sa * HH);
            float4 v1 = *(const float4*)(base + (size_t)sb * HH);
            a0.x += v0.x; a0.y += v0.y; a0.z += v0.z; a0.w += v0.w;
            a1.x += v1.x; a1.y += v1.y; a1.z += v1.z; a1.w += v1.w;
        }
        if (j < m) {
            int sa = __shfl_sync(0xffffffffu, idx, j);
            float4 v0 = *(const float4*)(base + (size_t)sa * HH);
            a0.x += v0.x; a0.y += v0.y; a0.z += v0.z; a0.w += v0.w;
        }
    }
    float inv = 1.f / fmaxf((float)(s1 - s0), 1.f);
    float4 acc = make_float4((a0.x + a1.x) * inv, (a0.y + a1.y) * inv,
                             (a0.z + a1.z) * inv, (a0.w + a1.w) * inv);
    *(float4*)&g_agg[(size_t)gw * HH + lane * 4] = acc;
}

// final layer: aggregate transformed 64-dim features (cols 0-63 of g_y),
// add self-branch (cols 64-127, bias applied), write to d_out
__global__ void __launch_bounds__(256) k_agg64_add(float* __restrict__ out) {
    int gw = (blockIdx.x * 256 + threadIdx.x) >> 5;
    if (gw >= NN) return;
    int lane = threadIdx.x & 31;
    int s0 = g_off[gw], s1 = g_off[gw + 1];
    const float* base = g_y + lane * 2;
    float2 a0 = make_float2(0.f, 0.f);
    float2 a1 = make_float2(0.f, 0.f);
    for (int b = s0; b < s1; b += 32) {
        int m = s1 - b; if (m > 32) m = 32;
        int idx = (lane < m) ? g_csr[b + lane] : 0;
        int j = 0;
        #pragma unroll 4
        for (; j + 2 <= m; j += 2) {
            int sa = __shfl_sync(0xffffffffu, idx, j);
            int sb = __shfl_sync(0xffffffffu, idx, j + 1);
            float2 v0 = *(const float2*)(base + (size_t)sa * HH);
            float2 v1 = *(const float2*)(base + (size_t)sb * HH);
            a0.x += v0.x; a0.y += v0.y;
            a1.x += v1.x; a1.y += v1.y;
        }
        if (j < m) {
            int sa = __shfl_sync(0xffffffffu, idx, j);
            float2 v0 = *(const float2*)(base + (size_t)sa * HH);
            a0.x += v0.x; a0.y += v0.y;
        }
    }
    float inv = 1.f / fmaxf((float)(s1 - s0), 1.f);
    float2 r = *(const float2*)&g_y[(size_t)gw * HH + 64 + lane * 2];
    float2 o = make_float2((a0.x + a1.x) * inv + r.x, (a0.y + a1.y) * inv + r.y);
    *(float2*)&out[(size_t)gw * OUTD + lane * 2] = o;
}

// ---------------- fp16 mma.sync GEMM (fp32 accumulate) ----------------
__device__ __forceinline__ void mma_16x8x16(float* c, const uint32_t* a, const uint32_t* b) {
    asm volatile(
        "mma.sync.aligned.m16n8k16.row.col.f32.f16.f16.f32 "
        "{%0,%1,%2,%3}, {%4,%5,%6,%7}, {%8,%9}, {%0,%1,%2,%3};"
        : "+f"(c[0]), "+f"(c[1]), "+f"(c[2]), "+f"(c[3])
        : "r"(a[0]), "r"(a[1]), "r"(a[2]), "r"(a[3]), "r"(b[0]), "r"(b[1]));
}

// Block: 256 threads = 8 warps (2 row x 4 col), tile 128x128, BK=32.
// Layers 0/1 (KCH=8, L2=false): g_y = [g_agg | A2] @ [Wl|Wr]^T + b  (K=256), fused BN stats
// Layer  2  (KCH=4, L2=true):   g_y = A2 @ [Wl2 ; Wr2]^T (N-concat), +b2 on cols>=64 (K=128)
template <int KCH, bool L2>
__global__ void __launch_bounds__(256)
k_gemm_mma(const float* __restrict__ xext, int use_h,
           const float* __restrict__ Wl, const float* __restrict__ Wr,
           const float* __restrict__ bias)
{
    constexpr int BK = 32, LDS_ = BK + 8;   // halves

    __shared__ __half As[128 * LDS_];
    __shared__ __half Bs[128 * LDS_];
    __shared__ float sbias[HH];
    __shared__ float ssum[HH], ssq[HH];

    const float* __restrict__ A2 = use_h ? g_h : xext;

    int tid = threadIdx.x;
    int wid = tid >> 5, lane = tid & 31;
    int wm = (wid & 1) * 64;        // warp row offset
    int wn = (wid >> 1) * 32;       // warp col offset
    int gid = lane >> 2;            // 0..7
    int tq  = lane & 3;             // 0..3
    int rowbase = blockIdx.x * 128;

    if (tid < HH) {
        if (L2) sbias[tid] = (tid >= OUTD) ? bias[tid - OUTD] : 0.f;
        else    sbias[tid] = bias[tid];
        ssum[tid] = 0.f; ssq[tid] = 0.f;
    }

    float c[4][4][4];
    #pragma unroll
    for (int i = 0; i < 4; i++)
        #pragma unroll
        for (int j = 0; j < 4; j++)
            #pragma unroll
            for (int k = 0; k < 4; k++) c[i][j][k] = 0.f;

    int lr = tid >> 3;              // 0..31 (load row)
    int lk = (tid & 7) * 4;         // 0,4,...,28 (load k)

    for (int kc = 0; kc < KCH; kc++) {
        const float* __restrict__ Asrc;
        int kb;
        if (L2) { Asrc = A2; kb = kc * BK; }
        else    { Asrc = (kc < 4) ? g_agg : A2; kb = (kc & 3) * BK; }

        #pragma unroll
        for (int it = 0; it < 4; it++) {
            int row = lr + it * 32;
            int r = rowbase + row;
            float4 v = make_float4(0.f, 0.f, 0.f, 0.f);
            if (r < NN) v = *(const float4*)&Asrc[(size_t)r * HH + kb + lk];
            __half2 h0 = __floats2half2_rn(v.x, v.y);
            __half2 h1 = __floats2half2_rn(v.z, v.w);
            *(__half2*)&As[row * LDS_ + lk]     = h0;
            *(__half2*)&As[row * LDS_ + lk + 2] = h1;
        }
        #pragma unroll
        for (int it = 0; it < 4; it++) {
            int n = lr + it * 32;
            const float* __restrict__ Wsrc;
            int wrow;
            if (L2) { Wsrc = (n < OUTD) ? Wl : Wr; wrow = n & (OUTD - 1); }
            else    { Wsrc = (kc < 4) ? Wl : Wr;   wrow = n; }
            float4 w = *(const float4*)&Wsrc[(size_t)wrow * HH + kb + lk];
            __half2 h0 = __floats2half2_rn(w.x, w.y);
            __half2 h1 = __floats2half2_rn(w.z, w.w);
            *(__half2*)&Bs[n * LDS_ + lk]     = h0;
            *(__half2*)&Bs[n * LDS_ + lk + 2] = h1;
        }
        __syncthreads();

        #pragma unroll
        for (int ks = 0; ks < BK / 16; ks++) {
            int k0 = ks * 16;
            uint32_t a[4][4], b[4][2];
            #pragma unroll
            for (int mi = 0; mi < 4; mi++) {
                const __half* p = &As[(wm + mi * 16 + gid) * LDS_ + k0 + tq * 2];
                a[mi][0] = *(const uint32_t*)p;
                a[mi][1] = *(const uint32_t*)(p + 8 * LDS_);
                a[mi][2] = *(const uint32_t*)(p + 8);
                a[mi][3] = *(const uint32_t*)(p + 8 * LDS_ + 8);
            }
            #pragma unroll
            for (int nj = 0; nj < 4; nj++) {
                const __half* p = &Bs[(wn + nj * 8 + gid) * LDS_ + k0 + tq * 2];
                b[nj][0] = *(const uint32_t*)p;
                b[nj][1] = *(const uint32_t*)(p + 8);
            }
            #pragma unroll
            for (int mi = 0; mi < 4; mi++)
                #pragma unroll
                for (int nj = 0; nj < 4; nj++)
                    mma_16x8x16(c[mi][nj], a[mi], b[nj]);
        }
        __syncthreads();
    }

    // epilogue: bias + store; fused BN column stats (layers 0/1)
    float ls[8], lq[8];
    #pragma unroll
    for (int j = 0; j < 8; j++) { ls[j] = 0.f; lq[j] = 0.f; }

    #pragma unroll
    for (int mi = 0; mi < 4; mi++) {
        int r0 = rowbase + wm + mi * 16 + gid;
        int r1 = r0 + 8;
        #pragma unroll
        for (int nj = 0; nj < 4; nj++) {
            int col = wn + nj * 8 + tq * 2;
            float bx = sbias[col], by = sbias[col + 1];
            if (r0 < NN) {
                float vx = c[mi][nj][0] + bx, vy = c[mi][nj][1] + by;
                *(float2*)&g_y[(size_t)r0 * HH + col] = make_float2(vx, vy);
                if (!L2) {
                    ls[nj * 2] += vx; lq[nj * 2] += vx * vx;
                    ls[nj * 2 + 1] += vy; lq[nj * 2 + 1] += vy * vy;
                }
            }
            if (r1 < NN) {
                float vx = c[mi][nj][2] + bx, vy = c[mi][nj][3] + by;
                *(float2*)&g_y[(size_t)r1 * HH + col] = make_float2(vx, vy);
                if (!L2) {
                    ls[nj * 2] += vx; lq[nj * 2] += vx * vx;
                    ls[nj * 2 + 1] += vy; lq[nj * 2 + 1] += vy * vy;
                }
            }
        }
    }

    if (!L2) {
        #pragma unroll
        for (int nj = 0; nj < 4; nj++) {
            int col = wn + nj * 8 + tq * 2;
            atomicAdd(&ssum[col],     ls[nj * 2]);
            atomicAdd(&ssq [col],     lq[nj * 2]);
            atomicAdd(&ssum[col + 1], ls[nj * 2 + 1]);
            atomicAdd(&ssq [col + 1], lq[nj * 2 + 1]);
        }
        __syncthreads();
        if (tid < HH) {
            atomicAdd(&g_sum[tid], ssum[tid]);
            atomicAdd(&g_sq [tid], ssq [tid]);
        }
    }
}

// ---------------- BN apply + ReLU: g_y -> g_h (float4) ----------------
__global__ void k_bn4(const float* __restrict__ gamma, const float* __restrict__ beta) {
    int i = blockIdx.x * blockDim.x + threadIdx.x;
    if (i >= NN * HH / 4) return;
    int o = (i & 31) * 4;
    const float invN = 1.0f / (float)NN;
    float4 y = *(const float4*)&g_y[(size_t)i * 4];
    float4 r;
    float mu, var, s;
    mu = g_sum[o + 0] * invN; var = g_sq[o + 0] * invN - mu * mu; s = rsqrtf(var + BN_EPS) * gamma[o + 0];
    r.x = fmaxf((y.x - mu) * s + beta[o + 0], 0.f);
    mu = g_sum[o + 1] * invN; var = g_sq[o + 1] * invN - mu * mu; s = rsqrtf(var + BN_EPS) * gamma[o + 1];
    r.y = fmaxf((y.y - mu) * s + beta[o + 1], 0.f);
    mu = g_sum[o + 2] * invN; var = g_sq[o + 2] * invN - mu * mu; s = rsqrtf(var + BN_EPS) * gamma[o + 2];
    r.z = fmaxf((y.z - mu) * s + beta[o + 2], 0.f);
    mu = g_sum[o + 3] * invN; var = g_sq[o + 3] * invN - mu * mu; s = rsqrtf(var + BN_EPS) * gamma[o + 3];
    r.w = fmaxf((y.w - mu) * s + beta[o + 3], 0.f);
    *(float4*)&g_h[(size_t)i * 4] = r;
}

// ---------------- launch ----------------
extern "C" void kernel_launch(void* const* d_in, const int* in_sizes, int n_in,
                              void* d_out, int out_size)
{
    const float* x   = (const float*)d_in[0];
    const int*   ei  = (const int*)d_in[1];
    const int*   src = ei;
    const int*   dst = ei + EE;
    const float* Wl0 = (const float*)d_in[2];
    const float* Wr0 = (const float*)d_in[3];
    const float* b0  = (const float*)d_in[4];
    const float* g0  = (const float*)d_in[5];
    const float* be0 = (const float*)d_in[6];
    const float* Wl1 = (const float*)d_in[7];
    const float* Wr1 = (const float*)d_in[8];
    const float* b1  = (const float*)d_in[9];
    const float* g1  = (const float*)d_in[10];
    const float* be1 = (const float*)d_in[11];
    const float* Wl2 = (const float*)d_in[12];
    const float* Wr2 = (const float*)d_in[13];
    const float* b2  = (const float*)d_in[14];
    float* out = (float*)d_out;

    const int TPB = 256;
    const int gE  = (EE + TPB - 1) / TPB;
    const int gN  = (NN + TPB - 1) / TPB;
    const int gG  = (NN + 127) / 128;
    const int gW  = (NN * 32 + TPB - 1) / TPB;
    const int gBN = (NN * HH / 4 + TPB - 1) / TPB;

    // CSR build (reused by all 3 layers)
    k_zero_deg<<<gN, TPB>>>();
    k_hist<<<gE, TPB>>>(dst);
    k_scan<<<1, 1024>>>();
    k_fill<<<gE, TPB>>>(src, dst);

    // layer 0
    k_agg128<<<gW, TPB>>>(x, 0);
    k_gemm_mma<8, false><<<gG, TPB>>>(x, 0, Wl0, Wr0, b0);
    k_bn4<<<gBN, TPB>>>(g0, be0);

    // layer 1
    k_agg128<<<gW, TPB>>>(nullptr, 1);
    k_gemm_mma<8, false><<<gG, TPB>>>(nullptr, 1, Wl1, Wr1, b1);
    k_bn4<<<gBN, TPB>>>(g1, be1);

    // layer 2: transform first (N-concat dual GEMM), then 64-dim aggregate + add
    k_gemm_mma<4, true><<<gG, TPB>>>(nullptr, 1, Wl2, Wr2, b2);
    k_agg64_add<<<gW, TPB>>>(out);
}

// round 6
// speedup vs baseline: 1.9124x; 1.0453x over previous
#include <cuda_runtime.h>
#include <cuda_fp16.h>
#include <cstdint>

#define NN 50000
#define EE 1600000
#define HH 128
#define OUTD 64
#define BN_EPS 1e-5f

// ---------------- device scratch (static, no allocation) ----------------
__device__ int    g_deg[NN];
__device__ int    g_off[NN + 1];
__device__ int    g_cur[NN];
__device__ int    g_csr[EE];
__device__ __half g_xh [(size_t)NN * HH];   // x in fp16
__device__ __half g_agg[(size_t)NN * HH];   // aggregated neighbors (fp16)
__device__ __half g_h  [(size_t)NN * HH];   // hidden activations (fp16)
__device__ float  g_y  [(size_t)NN * HH];   // pre-BN / layer-2 transform (fp32)
__device__ float  g_sum[HH];
__device__ float  g_sq [HH];

// ---------------- CSR build ----------------
__global__ void k_zero_deg() {
    int i = blockIdx.x * blockDim.x + threadIdx.x;
    if (i < NN) g_deg[i] = 0;
}

__global__ void k_hist(const int* __restrict__ dst) {
    int i = blockIdx.x * blockDim.x + threadIdx.x;
    if (i < EE) atomicAdd(&g_deg[dst[i]], 1);
}

__global__ void __launch_bounds__(1024) k_scan() {
    const int C = (NN + 1023) / 1024;
    int t = threadIdx.x;
    int lo = t * C, hi = min(lo + C, NN);
    int s = 0;
    for (int i = lo; i < hi; i++) s += g_deg[i];

    int lane = t & 31, wid = t >> 5;
    int v = s;
    #pragma unroll
    for (int d = 1; d < 32; d <<= 1) {
        int u = __shfl_up_sync(0xffffffffu, v, d);
        if (lane >= d) v += u;
    }
    __shared__ int wsum[32];
    if (lane == 31) wsum[wid] = v;
    __syncthreads();
    if (wid == 0) {
        int w = wsum[lane];
        #pragma unroll
        for (int d = 1; d < 32; d <<= 1) {
            int u = __shfl_up_sync(0xffffffffu, w, d);
            if (lane >= d) w += u;
        }
        wsum[lane] = w;
    }
    __syncthreads();
    int excl = v - s + (wid ? wsum[wid - 1] : 0);
    for (int i = lo; i < hi; i++) {
        g_off[i] = excl; g_cur[i] = excl;
        excl += g_deg[i];
    }
    if (t == 0) g_off[NN] = wsum[31];
}

__global__ void k_fill(const int* __restrict__ src, const int* __restrict__ dst) {
    int i = blockIdx.x * blockDim.x + threadIdx.x;
    if (i < EE) {
        int p = atomicAdd(&g_cur[dst[i]], 1);
        g_csr[p] = src[i];
    }
}

// ---------------- x -> fp16 ----------------
__global__ void k_x2h(const float* __restrict__ x) {
    int i = blockIdx.x * blockDim.x + threadIdx.x;
    if (i >= NN * HH / 4) return;
    float4 v = *(const float4*)&x[(size_t)i * 4];
    __half2 h0 = __floats2half2_rn(v.x, v.y);
    __half2 h1 = __floats2half2_rn(v.z, v.w);
    uint2 u = make_uint2(*(uint32_t*)&h0, *(uint32_t*)&h1);
    *(uint2*)&g_xh[(size_t)i * 4] = u;
}

// ---------------- aggregation: warp per node, fp16 gather, fp32 accumulate ----------------
__global__ void __launch_bounds__(256) k_agg128(int use_h) {
    if (blockIdx.x == 0 && threadIdx.x < HH) {
        g_sum[threadIdx.x] = 0.f;
        g_sq [threadIdx.x] = 0.f;
    }
    const __half* __restrict__ xin = use_h ? g_h : g_xh;
    int gw = (blockIdx.x * 256 + threadIdx.x) >> 5;
    if (gw >= NN) return;
    int lane = threadIdx.x & 31;
    int s0 = g_off[gw], s1 = g_off[gw + 1];
    const __half* base = xin + lane * 4;
    float4 a0 = make_float4(0.f, 0.f, 0.f, 0.f);
    float4 a1 = make_float4(0.f, 0.f, 0.f, 0.f);
    for (int b = s0; b < s1; b += 32) {
        int m = s1 - b; if (m > 32) m = 32;
        int idx = (lane < m) ? g_csr[b + lane] : 0;
        int j = 0;
        #pragma unroll 4
        for (; j + 2 <= m; j += 2) {
            int sa = __shfl_sync(0xffffffffu, idx, j);
            int sb = __shfl_sync(0xffffffffu, idx, j + 1);
            uint2 u0 = *(const uint2*)(base + (size_t)sa * HH);
            uint2 u1 = *(const uint2*)(base + (size_t)sb * HH);
            float2 p0 = __half22float2(*(__half2*)&u0.x);
            float2 p1 = __half22float2(*(__half2*)&u0.y);
            float2 q0 = __half22float2(*(__half2*)&u1.x);
            float2 q1 = __half22float2(*(__half2*)&u1.y);
            a0.x += p0.x; a0.y += p0.y; a0.z += p1.x; a0.w += p1.y;
            a1.x += q0.x; a1.y += q0.y; a1.z += q1.x; a1.w += q1.y;
        }
        if (j < m) {
            int sa = __shfl_sync(0xffffffffu, idx, j);
            uint2 u0 = *(const uint2*)(base + (size_t)sa * HH);
            float2 p0 = __half22float2(*(__half2*)&u0.x);
            float2 p1 = __half22float2(*(__half2*)&u0.y);
            a0.x += p0.x; a0.y += p0.y; a0.z += p1.x; a0.w += p1.y;
        }
    }
    float inv = 1.f / fmaxf((float)(s1 - s0), 1.f);
    __half2 h0 = __floats2half2_rn((a0.x + a1.x) * inv, (a0.y + a1.y) * inv);
    __half2 h1 = __floats2half2_rn((a0.z + a1.z) * inv, (a0.w + a1.w) * inv);
    uint2 u = make_uint2(*(uint32_t*)&h0, *(uint32_t*)&h1);
    *(uint2*)&g_agg[(size_t)gw * HH + lane * 4] = u;
}

// final layer: aggregate transformed 64-dim features (cols 0-63 of g_y, fp32),
// add self-branch (cols 64-127, bias applied), write to d_out
__global__ void __launch_bounds__(256) k_agg64_add(float* __restrict__ out) {
    int gw = (blockIdx.x * 256 + threadIdx.x) >> 5;
    if (gw >= NN) return;
    int lane = threadIdx.x & 31;
    int s0 = g_off[gw], s1 = g_off[gw + 1];
    const float* base = g_y + lane * 2;
    float2 a0 = make_float2(0.f, 0.f);
    float2 a1 = make_float2(0.f, 0.f);
    for (int b = s0; b < s1; b += 32) {
        int m = s1 - b; if (m > 32) m = 32;
        int idx = (lane < m) ? g_csr[b + lane] : 0;
        int j = 0;
        #pragma unroll 4
        for (; j + 2 <= m; j += 2) {
            int sa = __shfl_sync(0xffffffffu, idx, j);
            int sb = __shfl_sync(0xffffffffu, idx, j + 1);
            float2 v0 = *(const float2*)(base + (size_t)sa * HH);
            float2 v1 = *(const float2*)(base + (size_t)sb * HH);
            a0.x += v0.x; a0.y += v0.y;
            a1.x += v1.x; a1.y += v1.y;
        }
        if (j < m) {
            int sa = __shfl_sync(0xffffffffu, idx, j);
            float2 v0 = *(const float2*)(base + (size_t)sa * HH);
            a0.x += v0.x; a0.y += v0.y;
        }
    }
    float inv = 1.f / fmaxf((float)(s1 - s0), 1.f);
    float2 r = *(const float2*)&g_y[(size_t)gw * HH + 64 + lane * 2];
    float2 o = make_float2((a0.x + a1.x) * inv + r.x, (a0.y + a1.y) * inv + r.y);
    *(float2*)&out[(size_t)gw * OUTD + lane * 2] = o;
}

// ---------------- fp16 mma.sync GEMM (fp32 accumulate) ----------------
__device__ __forceinline__ void mma_16x8x16(float* c, const uint32_t* a, const uint32_t* b) {
    asm volatile(
        "mma.sync.aligned.m16n8k16.row.col.f32.f16.f16.f32 "
        "{%0,%1,%2,%3}, {%4,%5,%6,%7}, {%8,%9}, {%0,%1,%2,%3};"
        : "+f"(c[0]), "+f"(c[1]), "+f"(c[2]), "+f"(c[3])
        : "r"(a[0]), "r"(a[1]), "r"(a[2]), "r"(a[3]), "r"(b[0]), "r"(b[1]));
}

// Block: 256 threads = 8 warps (2 row x 4 col), tile 128x128, BK=32.
// Layers 0/1 (KCH=8, L2=false): g_y = [g_agg | A2h] @ [Wl|Wr]^T + b (K=256), fused BN stats
// Layer  2  (KCH=4, L2=true):   g_y = g_h @ [Wl2 ; Wr2]^T (N-concat), +b2 on cols>=64 (K=128)
template <int KCH, bool L2>
__global__ void __launch_bounds__(256)
k_gemm_mma(int use_h,
           const float* __restrict__ Wl, const float* __restrict__ Wr,
           const float* __restrict__ bias)
{
    constexpr int BK = 32, LDS_ = BK + 8;   // halves

    __shared__ __half As[128 * LDS_];
    __shared__ __half Bs[128 * LDS_];
    __shared__ float sbias[HH];
    __shared__ float ssum[HH], ssq[HH];

    const __half* __restrict__ A2h = use_h ? g_h : g_xh;

    int tid = threadIdx.x;
    int wid = tid >> 5, lane = tid & 31;
    int wm = (wid & 1) * 64;
    int wn = (wid >> 1) * 32;
    int gid = lane >> 2;
    int tq  = lane & 3;
    int rowbase = blockIdx.x * 128;

    if (tid < HH) {
        if (L2) sbias[tid] = (tid >= OUTD) ? bias[tid - OUTD] : 0.f;
        else    sbias[tid] = bias[tid];
        ssum[tid] = 0.f; ssq[tid] = 0.f;
    }

    float c[4][4][4];
    #pragma unroll
    for (int i = 0; i < 4; i++)
        #pragma unroll
        for (int j = 0; j < 4; j++)
            #pragma unroll
            for (int k = 0; k < 4; k++) c[i][j][k] = 0.f;

    int lr = tid >> 3;              // 0..31 (load row)
    int lk = (tid & 7) * 4;         // 0,4,...,28 (load k, halves)

    for (int kc = 0; kc < KCH; kc++) {
        const __half* __restrict__ Asrc;
        int kb;
        if (L2) { Asrc = A2h; kb = kc * BK; }
        else    { Asrc = (kc < 4) ? g_agg : A2h; kb = (kc & 3) * BK; }

        #pragma unroll
        for (int it = 0; it < 4; it++) {
            int row = lr + it * 32;
            int r = rowbase + row;
            uint2 v = make_uint2(0u, 0u);
            if (r < NN) v = *(const uint2*)&Asrc[(size_t)r * HH + kb + lk];
            *(uint2*)&As[row * LDS_ + lk] = v;
        }
        #pragma unroll
        for (int it = 0; it < 4; it++) {
            int n = lr + it * 32;
            const float* __restrict__ Wsrc;
            int wrow;
            if (L2) { Wsrc = (n < OUTD) ? Wl : Wr; wrow = n & (OUTD - 1); }
            else    { Wsrc = (kc < 4) ? Wl : Wr;   wrow = n; }
            float4 w = *(const float4*)&Wsrc[(size_t)wrow * HH + kb + lk];
            __half2 h0 = __floats2half2_rn(w.x, w.y);
            __half2 h1 = __floats2half2_rn(w.z, w.w);
            *(__half2*)&Bs[n * LDS_ + lk]     = h0;
            *(__half2*)&Bs[n * LDS_ + lk + 2] = h1;
        }
        __syncthreads();

        #pragma unroll
        for (int ks = 0; ks < BK / 16; ks++) {
            int k0 = ks * 16;
            uint32_t a[4][4], b[4][2];
            #pragma unroll
            for (int mi = 0; mi < 4; mi++) {
                const __half* p = &As[(wm + mi * 16 + gid) * LDS_ + k0 + tq * 2];
                a[mi][0] = *(const uint32_t*)p;
                a[mi][1] = *(const uint32_t*)(p + 8 * LDS_);
                a[mi][2] = *(const uint32_t*)(p + 8);
                a[mi][3] = *(const uint32_t*)(p + 8 * LDS_ + 8);
            }
            #pragma unroll
            for (int nj = 0; nj < 4; nj++) {
                const __half* p = &Bs[(wn + nj * 8 + gid) * LDS_ + k0 + tq * 2];
                b[nj][0] = *(const uint32_t*)p;
                b[nj][1] = *(const uint32_t*)(p + 8);
            }
            #pragma unroll
            for (int mi = 0; mi < 4; mi++)
                #pragma unroll
                for (int nj = 0; nj < 4; nj++)
                    mma_16x8x16(c[mi][nj], a[mi], b[nj]);
        }
        __syncthreads();
    }

    // epilogue: bias + store; fused BN column stats (layers 0/1)
    float ls[8], lq[8];
    #pragma unroll
    for (int j = 0; j < 8; j++) { ls[j] = 0.f; lq[j] = 0.f; }

    #pragma unroll
    for (int mi = 0; mi < 4; mi++) {
        int r0 = rowbase + wm + mi * 16 + gid;
        int r1 = r0 + 8;
        #pragma unroll
        for (int nj = 0; nj < 4; nj++) {
            int col = wn + nj * 8 + tq * 2;
            float bx = sbias[col], by = sbias[col + 1];
            if (r0 < NN) {
                float vx = c[mi][nj][0] + bx, vy = c[mi][nj][1] + by;
                *(float2*)&g_y[(size_t)r0 * HH + col] = make_float2(vx, vy);
                if (!L2) {
                    ls[nj * 2] += vx; lq[nj * 2] += vx * vx;
                    ls[nj * 2 + 1] += vy; lq[nj * 2 + 1] += vy * vy;
                }
            }
            if (r1 < NN) {
                float vx = c[mi][nj][2] + bx, vy = c[mi][nj][3] + by;
                *(float2*)&g_y[(size_t)r1 * HH + col] = make_float2(vx, vy);
                if (!L2) {
                    ls[nj * 2] += vx; lq[nj * 2] += vx * vx;
                    ls[nj * 2 + 1] += vy; lq[nj * 2 + 1] += vy * vy;
                }
            }
        }
    }

    if (!L2) {
        #pragma unroll
        for (int nj = 0; nj < 4; nj++) {
            int col = wn + nj * 8 + tq * 2;
            atomicAdd(&ssum[col],     ls[nj * 2]);
            atomicAdd(&ssq [col],     lq[nj * 2]);
            atomicAdd(&ssum[col + 1], ls[nj * 2 + 1]);
            atomicAdd(&ssq [col + 1], lq[nj * 2 + 1]);
        }
        __syncthreads();
        if (tid < HH) {
            atomicAdd(&g_sum[tid], ssum[tid]);
            atomicAdd(&g_sq [tid], ssq [tid]);
        }
    }
}

// ---------------- BN apply + ReLU: g_y (fp32) -> g_h (fp16) ----------------
__global__ void k_bn4(const float* __restrict__ gamma, const float* __restrict__ beta) {
    int i = blockIdx.x * blockDim.x + threadIdx.x;
    if (i >= NN * HH / 4) return;
    int o = (i & 31) * 4;
    const float invN = 1.0f / (float)NN;
    float4 y = *(const float4*)&g_y[(size_t)i * 4];
    float r0, r1, r2, r3;
    float mu, var, s;
    mu = g_sum[o + 0] * invN; var = g_sq[o + 0] * invN - mu * mu; s = rsqrtf(var + BN_EPS) * gamma[o + 0];
    r0 = fmaxf((y.x - mu) * s + beta[o + 0], 0.f);
    mu = g_sum[o + 1] * invN; var = g_sq[o + 1] * invN - mu * mu; s = rsqrtf(var + BN_EPS) * gamma[o + 1];
    r1 = fmaxf((y.y - mu) * s + beta[o + 1], 0.f);
    mu = g_sum[o + 2] * invN; var = g_sq[o + 2] * invN - mu * mu; s = rsqrtf(var + BN_EPS) * gamma[o + 2];
    r2 = fmaxf((y.z - mu) * s + beta[o + 2], 0.f);
    mu = g_sum[o + 3] * invN; var = g_sq[o + 3] * invN - mu * mu; s = rsqrtf(var + BN_EPS) * gamma[o + 3];
    r3 = fmaxf((y.w - mu) * s + beta[o + 3], 0.f);
    __half2 h0 = __floats2half2_rn(r0, r1);
    __half2 h1 = __floats2half2_rn(r2, r3);
    uint2 u = make_uint2(*(uint32_t*)&h0, *(uint32_t*)&h1);
    *(uint2*)&g_h[(size_t)i * 4] = u;
}

// ---------------- launch ----------------
extern "C" void kernel_launch(void* const* d_in, const int* in_sizes, int n_in,
                              void* d_out, int out_size)
{
    const float* x   = (const float*)d_in[0];
    const int*   ei  = (const int*)d_in[1];
    const int*   src = ei;
    const int*   dst = ei + EE;
    const float* Wl0 = (const float*)d_in[2];
    const float* Wr0 = (const float*)d_in[3];
    const float* b0  = (const float*)d_in[4];
    const float* g0  = (const float*)d_in[5];
    const float* be0 = (const float*)d_in[6];
    const float* Wl1 = (const float*)d_in[7];
    const float* Wr1 = (const float*)d_in[8];
    const float* b1  = (const float*)d_in[9];
    const float* g1  = (const float*)d_in[10];
    const float* be1 = (const float*)d_in[11];
    const float* Wl2 = (const float*)d_in[12];
    const float* Wr2 = (const float*)d_in[13];
    const float* b2  = (const float*)d_in[14];
    float* out = (float*)d_out;

    const int TPB = 256;
    const int gE  = (EE + TPB - 1) / TPB;
    const int gN  = (NN + TPB - 1) / TPB;
    const int gG  = (NN + 127) / 128;
    const int gW  = (NN * 32 + TPB - 1) / TPB;
    const int gBN = (NN * HH / 4 + TPB - 1) / TPB;

    // CSR build + x->fp16 (CSR reused by all 3 layers)
    k_zero_deg<<<gN, TPB>>>();
    k_hist<<<gE, TPB>>>(dst);
    k_x2h<<<gBN, TPB>>>(x);
    k_scan<<<1, 1024>>>();
    k_fill<<<gE, TPB>>>(src, dst);

    // layer 0
    k_agg128<<<gW, TPB>>>(0);
    k_gemm_mma<8, false><<<gG, TPB>>>(0, Wl0, Wr0, b0);
    k_bn4<<<gBN, TPB>>>(g0, be0);

    // layer 1
    k_agg128<<<gW, TPB>>>(1);
    k_gemm_mma<8, false><<<gG, TPB>>>(1, Wl1, Wr1, b1);
    k_bn4<<<gBN, TPB>>>(g1, be1);

    // layer 2: transform first (N-concat dual GEMM), then 64-dim aggregate + add
    k_gemm_mma<4, true><<<gG, TPB>>>(1, Wl2, Wr2, b2);
    k_agg64_add<<<gW, TPB>>>(out);
}

// round 7
// speedup vs baseline: 2.4180x; 1.2644x over previous
#include <cuda_runtime.h>
#include <cuda_fp16.h>
#include <cstdint>

#define NN 50000
#define EE 1600000
#define HH 128
#define OUTD 64
#define BN_EPS 1e-5f
#define NB_SCAN 49   // ceil(NN / 1024)

// ---------------- device scratch (static, no allocation) ----------------
__device__ int    g_deg[NN];
__device__ int    g_off[NN + 1];
__device__ int    g_cur[NN];
__device__ int    g_csr[EE];
__device__ int    g_bsum[NB_SCAN];
__device__ int    g_boff[NB_SCAN];
__device__ __half g_xh [(size_t)NN * HH];   // x in fp16
__device__ __half g_agg[(size_t)NN * HH];   // aggregated neighbors (fp16)
__device__ __half g_h  [(size_t)NN * HH];   // hidden activations (fp16)
__device__ float  g_y  [(size_t)NN * HH];   // pre-BN / layer-2 transform (fp32)
__device__ float  g_sum[HH];
__device__ float  g_sq [HH];

// ---------------- CSR build ----------------
__global__ void k_zero_deg() {
    int i = blockIdx.x * blockDim.x + threadIdx.x;
    if (i < NN) g_deg[i] = 0;
}

__global__ void k_hist(const int* __restrict__ dst) {
    int i = blockIdx.x * blockDim.x + threadIdx.x;
    if (i < EE) atomicAdd(&g_deg[dst[i]], 1);
}

// phase 1: per-block sum of degrees
__global__ void __launch_bounds__(1024) k_scan1() {
    int t = threadIdx.x, lane = t & 31, wid = t >> 5;
    int i = blockIdx.x * 1024 + t;
    int v = (i < NN) ? g_deg[i] : 0;
    #pragma unroll
    for (int d = 16; d > 0; d >>= 1) v += __shfl_down_sync(0xffffffffu, v, d);
    __shared__ int ws[32];
    if (lane == 0) ws[wid] = v;
    __syncthreads();
    if (wid == 0) {
        int w = ws[lane];
        #pragma unroll
        for (int d = 16; d > 0; d >>= 1) w += __shfl_down_sync(0xffffffffu, w, d);
        if (lane == 0) g_bsum[blockIdx.x] = w;
    }
}

// phase 2: exclusive scan of NB_SCAN block sums (one warp, 2 elems/lane)
__global__ void k_scan2() {
    int lane = threadIdx.x;
    int a = (lane < NB_SCAN) ? g_bsum[lane] : 0;
    int b = (lane + 32 < NB_SCAN) ? g_bsum[lane + 32] : 0;
    int ia = a;
    #pragma unroll
    for (int d = 1; d < 32; d <<= 1) {
        int u = __shfl_up_sync(0xffffffffu, ia, d);
        if (lane >= d) ia += u;
    }
    int tot_a = __shfl_sync(0xffffffffu, ia, 31);
    int ib = b;
    #pragma unroll
    for (int d = 1; d < 32; d <<= 1) {
        int u = __shfl_up_sync(0xffffffffu, ib, d);
        if (lane >= d) ib += u;
    }
    if (lane < NB_SCAN) g_boff[lane] = ia - a;
    if (lane + 32 < NB_SCAN) g_boff[lane + 32] = tot_a + ib - b;
}

// phase 3: block-wide exclusive scan + block offset -> g_off, g_cur
__global__ void __launch_bounds__(1024) k_scan3() {
    int t = threadIdx.x, lane = t & 31, wid = t >> 5;
    int i = blockIdx.x * 1024 + t;
    int v = (i < NN) ? g_deg[i] : 0;
    int inc = v;
    #pragma unroll
    for (int d = 1; d < 32; d <<= 1) {
        int u = __shfl_up_sync(0xffffffffu, inc, d);
        if (lane >= d) inc += u;
    }
    __shared__ int ws[32];
    if (lane == 31) ws[wid] = inc;
    __syncthreads();
    if (wid == 0) {
        int w = ws[lane];
        #pragma unroll
        for (int d = 1; d < 32; d <<= 1) {
            int u = __shfl_up_sync(0xffffffffu, w, d);
            if (lane >= d) w += u;
        }
        ws[lane] = w;
    }
    __syncthreads();
    int excl = inc - v + (wid ? ws[wid - 1] : 0) + g_boff[blockIdx.x];
    if (i < NN) {
        g_off[i] = excl;
        g_cur[i] = excl;
        if (i == NN - 1) g_off[NN] = excl + v;
    }
}

__global__ void k_fill(const int* __restrict__ src, const int* __restrict__ dst) {
    int i = blockIdx.x * blockDim.x + threadIdx.x;
    if (i < EE) {
        int p = atomicAdd(&g_cur[dst[i]], 1);
        g_csr[p] = src[i];
    }
}

// ---------------- x -> fp16 ----------------
__global__ void k_x2h(const float* __restrict__ x) {
    int i = blockIdx.x * blockDim.x + threadIdx.x;
    if (i >= NN * HH / 4) return;
    float4 v = *(const float4*)&x[(size_t)i * 4];
    __half2 h0 = __floats2half2_rn(v.x, v.y);
    __half2 h1 = __floats2half2_rn(v.z, v.w);
    uint2 u = make_uint2(*(uint32_t*)&h0, *(uint32_t*)&h1);
    *(uint2*)&g_xh[(size_t)i * 4] = u;
}

// ---------------- aggregation: warp per node, fp16 gather, fp32 accumulate ----------------
__global__ void __launch_bounds__(256) k_agg128(int use_h) {
    if (blockIdx.x == 0 && threadIdx.x < HH) {
        g_sum[threadIdx.x] = 0.f;
        g_sq [threadIdx.x] = 0.f;
    }
    const __half* __restrict__ xin = use_h ? g_h : g_xh;
    int gw = (blockIdx.x * 256 + threadIdx.x) >> 5;
    if (gw >= NN) return;
    int lane = threadIdx.x & 31;
    int s0 = g_off[gw], s1 = g_off[gw + 1];
    const __half* base = xin + lane * 4;
    float4 a0 = make_float4(0.f, 0.f, 0.f, 0.f);
    float4 a1 = make_float4(0.f, 0.f, 0.f, 0.f);
    for (int b = s0; b < s1; b += 32) {
        int m = s1 - b; if (m > 32) m = 32;
        int idx = (lane < m) ? g_csr[b + lane] : 0;
        int j = 0;
        #pragma unroll 4
        for (; j + 2 <= m; j += 2) {
            int sa = __shfl_sync(0xffffffffu, idx, j);
            int sb = __shfl_sync(0xffffffffu, idx, j + 1);
            uint2 u0 = *(const uint2*)(base + (size_t)sa * HH);
            uint2 u1 = *(const uint2*)(base + (size_t)sb * HH);
            float2 p0 = __half22float2(*(__half2*)&u0.x);
            float2 p1 = __half22float2(*(__half2*)&u0.y);
            float2 q0 = __half22float2(*(__half2*)&u1.x);
            float2 q1 = __half22float2(*(__half2*)&u1.y);
            a0.x += p0.x; a0.y += p0.y; a0.z += p1.x; a0.w += p1.y;
            a1.x += q0.x; a1.y += q0.y; a1.z += q1.x; a1.w += q1.y;
        }
        if (j < m) {
            int sa = __shfl_sync(0xffffffffu, idx, j);
            uint2 u0 = *(const uint2*)(base + (size_t)sa * HH);
            float2 p0 = __half22float2(*(__half2*)&u0.x);
            float2 p1 = __half22float2(*(__half2*)&u0.y);
            a0.x += p0.x; a0.y += p0.y; a0.z += p1.x; a0.w += p1.y;
        }
    }
    float inv = 1.f / fmaxf((float)(s1 - s0), 1.f);
    __half2 h0 = __floats2half2_rn((a0.x + a1.x) * inv, (a0.y + a1.y) * inv);
    __half2 h1 = __floats2half2_rn((a0.z + a1.z) * inv, (a0.w + a1.w) * inv);
    uint2 u = make_uint2(*(uint32_t*)&h0, *(uint32_t*)&h1);
    *(uint2*)&g_agg[(size_t)gw * HH + lane * 4] = u;
}

// final layer: aggregate transformed 64-dim features (cols 0-63 of g_y, fp32),
// add self-branch (cols 64-127, bias applied), write to d_out
__global__ void __launch_bounds__(256) k_agg64_add(float* __restrict__ out) {
    int gw = (blockIdx.x * 256 + threadIdx.x) >> 5;
    if (gw >= NN) return;
    int lane = threadIdx.x & 31;
    int s0 = g_off[gw], s1 = g_off[gw + 1];
    const float* base = g_y + lane * 2;
    float2 a0 = make_float2(0.f, 0.f);
    float2 a1 = make_float2(0.f, 0.f);
    for (int b = s0; b < s1; b += 32) {
        int m = s1 - b; if (m > 32) m = 32;
        int idx = (lane < m) ? g_csr[b + lane] : 0;
        int j = 0;
        #pragma unroll 4
        for (; j + 2 <= m; j += 2) {
            int sa = __shfl_sync(0xffffffffu, idx, j);
            int sb = __shfl_sync(0xffffffffu, idx, j + 1);
            float2 v0 = *(const float2*)(base + (size_t)sa * HH);
            float2 v1 = *(const float2*)(base + (size_t)sb * HH);
            a0.x += v0.x; a0.y += v0.y;
            a1.x += v1.x; a1.y += v1.y;
        }
        if (j < m) {
            int sa = __shfl_sync(0xffffffffu, idx, j);
            float2 v0 = *(const float2*)(base + (size_t)sa * HH);
            a0.x += v0.x; a0.y += v0.y;
        }
    }
    float inv = 1.f / fmaxf((float)(s1 - s0), 1.f);
    float2 r = *(const float2*)&g_y[(size_t)gw * HH + 64 + lane * 2];
    float2 o = make_float2((a0.x + a1.x) * inv + r.x, (a0.y + a1.y) * inv + r.y);
    *(float2*)&out[(size_t)gw * OUTD + lane * 2] = o;
}

// ---------------- fp16 mma.sync GEMM (fp32 accumulate) ----------------
__device__ __forceinline__ void mma_16x8x16(float* c, const uint32_t* a, const uint32_t* b) {
    asm volatile(
        "mma.sync.aligned.m16n8k16.row.col.f32.f16.f16.f32 "
        "{%0,%1,%2,%3}, {%4,%5,%6,%7}, {%8,%9}, {%0,%1,%2,%3};"
        : "+f"(c[0]), "+f"(c[1]), "+f"(c[2]), "+f"(c[3])
        : "r"(a[0]), "r"(a[1]), "r"(a[2]), "r"(a[3]), "r"(b[0]), "r"(b[1]));
}

// Block: 256 threads = 8 warps (2 row x 4 col), tile 128x128, BK=32.
// Layers 0/1 (KCH=8, L2=false): g_y = [g_agg | A2h] @ [Wl|Wr]^T + b (K=256), fused BN stats
// Layer  2  (KCH=4, L2=true):   g_y = g_h @ [Wl2 ; Wr2]^T (N-concat), +b2 on cols>=64 (K=128)
template <int KCH, bool L2>
__global__ void __launch_bounds__(256)
k_gemm_mma(int use_h,
           const float* __restrict__ Wl, const float* __restrict__ Wr,
           const float* __restrict__ bias)
{
    constexpr int BK = 32, LDS_ = BK + 8;   // halves

    __shared__ __half As[128 * LDS_];
    __shared__ __half Bs[128 * LDS_];
    __shared__ float sbias[HH];
    __shared__ float ssum[HH], ssq[HH];

    const __half* __restrict__ A2h = use_h ? g_h : g_xh;

    int tid = threadIdx.x;
    int wid = tid >> 5, lane = tid & 31;
    int wm = (wid & 1) * 64;
    int wn = (wid >> 1) * 32;
    int gid = lane >> 2;
    int tq  = lane & 3;
    int rowbase = blockIdx.x * 128;

    if (tid < HH) {
        if (L2) sbias[tid] = (tid >= OUTD) ? bias[tid - OUTD] : 0.f;
        else    sbias[tid] = bias[tid];
        ssum[tid] = 0.f; ssq[tid] = 0.f;
    }

    float c[4][4][4];
    #pragma unroll
    for (int i = 0; i < 4; i++)
        #pragma unroll
        for (int j = 0; j < 4; j++)
            #pragma unroll
            for (int k = 0; k < 4; k++) c[i][j][k] = 0.f;

    int lr = tid >> 3;              // 0..31 (load row)
    int lk = (tid & 7) * 4;         // 0,4,...,28 (load k, halves)

    for (int kc = 0; kc < KCH; kc++) {
        const __half* __restrict__ Asrc;
        int kb;
        if (L2) { Asrc = A2h; kb = kc * BK; }
        else    { Asrc = (kc < 4) ? g_agg : A2h; kb = (kc & 3) * BK; }

        #pragma unroll
        for (int it = 0; it < 4; it++) {
            int row = lr + it * 32;
            int r = rowbase + row;
            uint2 v = make_uint2(0u, 0u);
            if (r < NN) v = *(const uint2*)&Asrc[(size_t)r * HH + kb + lk];
            *(uint2*)&As[row * LDS_ + lk] = v;
        }
        #pragma unroll
        for (int it = 0; it < 4; it++) {
            int n = lr + it * 32;
            const float* __restrict__ Wsrc;
            int wrow;
            if (L2) { Wsrc = (n < OUTD) ? Wl : Wr; wrow = n & (OUTD - 1); }
            else    { Wsrc = (kc < 4) ? Wl : Wr;   wrow = n; }
            float4 w = *(const float4*)&Wsrc[(size_t)wrow * HH + kb + lk];
            __half2 h0 = __floats2half2_rn(w.x, w.y);
            __half2 h1 = __floats2half2_rn(w.z, w.w);
            *(__half2*)&Bs[n * LDS_ + lk]     = h0;
            *(__half2*)&Bs[n * LDS_ + lk + 2] = h1;
        }
        __syncthreads();

        #pragma unroll
        for (int ks = 0; ks < BK / 16; ks++) {
            int k0 = ks * 16;
            uint32_t a[4][4], b[4][2];
            #pragma unroll
            for (int mi = 0; mi < 4; mi++) {
                const __half* p = &As[(wm + mi * 16 + gid) * LDS_ + k0 + tq * 2];
                a[mi][0] = *(const uint32_t*)p;
                a[mi][1] = *(const uint32_t*)(p + 8 * LDS_);
                a[mi][2] = *(const uint32_t*)(p + 8);
                a[mi][3] = *(const uint32_t*)(p + 8 * LDS_ + 8);
            }
            #pragma unroll
            for (int nj = 0; nj < 4; nj++) {
                const __half* p = &Bs[(wn + nj * 8 + gid) * LDS_ + k0 + tq * 2];
                b[nj][0] = *(const uint32_t*)p;
                b[nj][1] = *(const uint32_t*)(p + 8);
            }
            #pragma unroll
            for (int mi = 0; mi < 4; mi++)
                #pragma unroll
                for (int nj = 0; nj < 4; nj++)
                    mma_16x8x16(c[mi][nj], a[mi], b[nj]);
        }
        __syncthreads();
    }

    // epilogue: bias + store; fused BN column stats (layers 0/1)
    float ls[8], lq[8];
    #pragma unroll
    for (int j = 0; j < 8; j++) { ls[j] = 0.f; lq[j] = 0.f; }

    #pragma unroll
    for (int mi = 0; mi < 4; mi++) {
        int r0 = rowbase + wm + mi * 16 + gid;
        int r1 = r0 + 8;
        #pragma unroll
        for (int nj = 0; nj < 4; nj++) {
            int col = wn + nj * 8 + tq * 2;
            float bx = sbias[col], by = sbias[col + 1];
            if (r0 < NN) {
                float vx = c[mi][nj][0] + bx, vy = c[mi][nj][1] + by;
                *(float2*)&g_y[(size_t)r0 * HH + col] = make_float2(vx, vy);
                if (!L2) {
                    ls[nj * 2] += vx; lq[nj * 2] += vx * vx;
                    ls[nj * 2 + 1] += vy; lq[nj * 2 + 1] += vy * vy;
                }
            }
            if (r1 < NN) {
                float vx = c[mi][nj][2] + bx, vy = c[mi][nj][3] + by;
                *(float2*)&g_y[(size_t)r1 * HH + col] = make_float2(vx, vy);
                if (!L2) {
                    ls[nj * 2] += vx; lq[nj * 2] += vx * vx;
                    ls[nj * 2 + 1] += vy; lq[nj * 2 + 1] += vy * vy;
                }
            }
        }
    }

    if (!L2) {
        #pragma unroll
        for (int nj = 0; nj < 4; nj++) {
            int col = wn + nj * 8 + tq * 2;
            atomicAdd(&ssum[col],     ls[nj * 2]);
            atomicAdd(&ssq [col],     lq[nj * 2]);
            atomicAdd(&ssum[col + 1], ls[nj * 2 + 1]);
            atomicAdd(&ssq [col + 1], lq[nj * 2 + 1]);
        }
        __syncthreads();
        if (tid < HH) {
            atomicAdd(&g_sum[tid], ssum[tid]);
            atomicAdd(&g_sq [tid], ssq [tid]);
        }
    }
}

// ---------------- BN apply + ReLU: g_y (fp32) -> g_h (fp16) ----------------
__global__ void k_bn4(const float* __restrict__ gamma, const float* __restrict__ beta) {
    int i = blockIdx.x * blockDim.x + threadIdx.x;
    if (i >= NN * HH / 4) return;
    int o = (i & 31) * 4;
    const float invN = 1.0f / (float)NN;
    float4 y = *(const float4*)&g_y[(size_t)i * 4];
    float r0, r1, r2, r3;
    float mu, var, s;
    mu = g_sum[o + 0] * invN; var = g_sq[o + 0] * invN - mu * mu; s = rsqrtf(var + BN_EPS) * gamma[o + 0];
    r0 = fmaxf((y.x - mu) * s + beta[o + 0], 0.f);
    mu = g_sum[o + 1] * invN; var = g_sq[o + 1] * invN - mu * mu; s = rsqrtf(var + BN_EPS) * gamma[o + 1];
    r1 = fmaxf((y.y - mu) * s + beta[o + 1], 0.f);
    mu = g_sum[o + 2] * invN; var = g_sq[o + 2] * invN - mu * mu; s = rsqrtf(var + BN_EPS) * gamma[o + 2];
    r2 = fmaxf((y.z - mu) * s + beta[o + 2], 0.f);
    mu = g_sum[o + 3] * invN; var = g_sq[o + 3] * invN - mu * mu; s = rsqrtf(var + BN_EPS) * gamma[o + 3];
    r3 = fmaxf((y.w - mu) * s + beta[o + 3], 0.f);
    __half2 h0 = __floats2half2_rn(r0, r1);
    __half2 h1 = __floats2half2_rn(r2, r3);
    uint2 u = make_uint2(*(uint32_t*)&h0, *(uint32_t*)&h1);
    *(uint2*)&g_h[(size_t)i * 4] = u;
}

// ---------------- launch ----------------
extern "C" void kernel_launch(void* const* d_in, const int* in_sizes, int n_in,
                              void* d_out, int out_size)
{
    const float* x   = (const float*)d_in[0];
    const int*   ei  = (const int*)d_in[1];
    const int*   src = ei;
    const int*   dst = ei + EE;
    const float* Wl0 = (const float*)d_in[2];
    const float* Wr0 = (const float*)d_in[3];
    const float* b0  = (const float*)d_in[4];
    const float* g0  = (const float*)d_in[5];
    const float* be0 = (const float*)d_in[6];
    const float* Wl1 = (const float*)d_in[7];
    const float* Wr1 = (const float*)d_in[8];
    const float* b1  = (const float*)d_in[9];
    const float* g1  = (const float*)d_in[10];
    const float* be1 = (const float*)d_in[11];
    const float* Wl2 = (const float*)d_in[12];
    const float* Wr2 = (const float*)d_in[13];
    const float* b2  = (const float*)d_in[14];
    float* out = (float*)d_out;

    const int TPB = 256;
    const int gE  = (EE + TPB - 1) / TPB;
    const int gN  = (NN + TPB - 1) / TPB;
    const int gG  = (NN + 127) / 128;
    const int gW  = (NN * 32 + TPB - 1) / TPB;
    const int gBN = (NN * HH / 4 + TPB - 1) / TPB;

    // CSR build + x->fp16 (CSR reused by all 3 layers)
    k_zero_deg<<<gN, TPB>>>();
    k_hist<<<gE, TPB>>>(dst);
    k_x2h<<<gBN, TPB>>>(x);
    k_scan1<<<NB_SCAN, 1024>>>();
    k_scan2<<<1, 32>>>();
    k_scan3<<<NB_SCAN, 1024>>>();
    k_fill<<<gE, TPB>>>(src, dst);

    // layer 0
    k_agg128<<<gW, TPB>>>(0);
    k_gemm_mma<8, false><<<gG, TPB>>>(0, Wl0, Wr0, b0);
    k_bn4<<<gBN, TPB>>>(g0, be0);

    // layer 1
    k_agg128<<<gW, TPB>>>(1);
    k_gemm_mma<8, false><<<gG, TPB>>>(1, Wl1, Wr1, b1);
    k_bn4<<<gBN, TPB>>>(g1, be1);

    // layer 2: transform first (N-concat dual GEMM), then 64-dim aggregate + add
    k_gemm_mma<4, true><<<gG, TPB>>>(1, Wl2, Wr2, b2);
    k_agg64_add<<<gW, TPB>>>(out);
}